// round 1
// baseline (speedup 1.0000x reference)
#include <cuda_runtime.h>
#include <math.h>

#define BB 2
#define CC 128
#define NP 2048
#define HH 4
#define DD 32
#define KNN 20
#define C2 256

// ---------------- scratch (single __device__ arena, no allocations) ----------------
// offsets in floats
#define O_QT   0                              // B*N*C  (q transposed: [b][n][c])
#define O_KT   (O_QT + BB*NP*CC)              // B*N*C
#define O_VT   (O_KT + BB*NP*CC)              // B*N*C
#define O_XX   (O_VT + BB*NP*CC)              // B*N
#define O_AV   (O_XX + BB*NP)                 // B*C*N
#define O_CAT  (O_AV + BB*CC*NP)              // B*2C*N
#define O_H    (O_CAT + BB*C2*NP)             // B*2C*N
#define O_MU   (O_H + BB*C2*NP)               // 2C
#define O_ISTD (O_MU + C2)                    // 2C
#define O_IDX  (O_ISTD + C2)                  // B*N*KNN ints (stored in float slots)
#define O_PD   (O_IDX + BB*NP*KNN)            // B*N*N
#define TOTALF (O_PD + (size_t)BB*NP*NP)

__device__ float g_buf[TOTALF];

// ---------------- xx[b][n] = sum_c x^2 ----------------
__global__ void xx_kernel(const float* __restrict__ x) {
    int i = blockIdx.x * blockDim.x + threadIdx.x;
    if (i >= BB * NP) return;
    int b = i / NP, n = i - b * NP;
    const float* xb = x + (size_t)b * CC * NP + n;
    float s = 0.f;
#pragma unroll 8
    for (int c = 0; c < CC; c++) { float v = xb[(size_t)c * NP]; s = fmaf(v, v, s); }
    g_buf[O_XX + i] = s;
}

// ---------------- generic conv1x1 GEMM: Y[b,o,n] = sum_c W[o,c] X[b,c,n] + bias[o] ----------------
// TRANS_OUT: write Y[b][n][o] (stride O). BN_IN: apply batchnorm+relu to X elements
// on load (using g_buf[O_MU/O_ISTD] + gamma/beta). RES: add resid[b][o][n].
template<int CIN, bool TRANS_OUT, bool BN_IN, bool RES>
__global__ void gemm_conv(const float* __restrict__ W, const float* __restrict__ bias,
                          const float* __restrict__ X, float* __restrict__ Y,
                          int O, int out_batch_stride, int out_row_off,
                          const float* __restrict__ resid,
                          const float* __restrict__ gamma, const float* __restrict__ beta)
{
    __shared__ float Ws[32][68];
    __shared__ float Xs[32][68];
    int b = blockIdx.z;
    int obase = blockIdx.y * 64, nbase = blockIdx.x * 64;
    int tid = threadIdx.x;
    const float* Xb = X + (size_t)b * CIN * NP;
    float acc[4][4] = {};
    int to = (tid >> 4) * 4, tn = (tid & 15) * 4;

    for (int kb = 0; kb < CIN; kb += 32) {
#pragma unroll
        for (int i = 0; i < 2; i++) {
            int g = tid + i * 256;
            int o = g & 63, kq = g >> 6;
            float4 w4 = *(const float4*)(W + (size_t)(obase + o) * CIN + kb + kq * 4);
            Ws[kq * 4 + 0][o] = w4.x; Ws[kq * 4 + 1][o] = w4.y;
            Ws[kq * 4 + 2][o] = w4.z; Ws[kq * 4 + 3][o] = w4.w;
        }
#pragma unroll
        for (int i = 0; i < 2; i++) {
            int g = tid + i * 256;
            int n4 = g & 15, kk = g >> 4;
            int c = kb + kk;
            float4 x4 = *(const float4*)(Xb + (size_t)c * NP + nbase + n4 * 4);
            if (BN_IN) {
                float m = g_buf[O_MU + c], is = g_buf[O_ISTD + c];
                float ga = gamma[c], be = beta[c];
                x4.x = fmaxf(fmaf((x4.x - m) * is, ga, be), 0.f);
                x4.y = fmaxf(fmaf((x4.y - m) * is, ga, be), 0.f);
                x4.z = fmaxf(fmaf((x4.z - m) * is, ga, be), 0.f);
                x4.w = fmaxf(fmaf((x4.w - m) * is, ga, be), 0.f);
            }
            *(float4*)&Xs[kk][n4 * 4] = x4;
        }
        __syncthreads();
#pragma unroll
        for (int k = 0; k < 32; k++) {
            float4 a = *(const float4*)&Ws[k][to];
            float4 v = *(const float4*)&Xs[k][tn];
            acc[0][0] = fmaf(a.x, v.x, acc[0][0]); acc[0][1] = fmaf(a.x, v.y, acc[0][1]);
            acc[0][2] = fmaf(a.x, v.z, acc[0][2]); acc[0][3] = fmaf(a.x, v.w, acc[0][3]);
            acc[1][0] = fmaf(a.y, v.x, acc[1][0]); acc[1][1] = fmaf(a.y, v.y, acc[1][1]);
            acc[1][2] = fmaf(a.y, v.z, acc[1][2]); acc[1][3] = fmaf(a.y, v.w, acc[1][3]);
            acc[2][0] = fmaf(a.z, v.x, acc[2][0]); acc[2][1] = fmaf(a.z, v.y, acc[2][1]);
            acc[2][2] = fmaf(a.z, v.z, acc[2][2]); acc[2][3] = fmaf(a.z, v.w, acc[2][3]);
            acc[3][0] = fmaf(a.w, v.x, acc[3][0]); acc[3][1] = fmaf(a.w, v.y, acc[3][1]);
            acc[3][2] = fmaf(a.w, v.z, acc[3][2]); acc[3][3] = fmaf(a.w, v.w, acc[3][3]);
        }
        __syncthreads();
    }
#pragma unroll
    for (int i = 0; i < 4; i++) {
        int o = obase + to + i;
        float bs = bias[o];
#pragma unroll
        for (int j = 0; j < 4; j++) {
            int n = nbase + tn + j;
            float v = acc[i][j] + bs;
            if (RES) v += resid[(size_t)b * CC * NP + (size_t)o * NP + n];
            if (TRANS_OUT)
                Y[((size_t)b * NP + n) * O + o] = v;
            else
                Y[(size_t)b * out_batch_stride + (size_t)(out_row_off + o) * NP + n] = v;
        }
    }
}

// ---------------- pd[b][n][m] = 2 x_n . x_m - xx_n - xx_m  (upper-tri blocks + mirror) ----------------
__global__ void pd_kernel(const float* __restrict__ x) {
    __shared__ float As[32][68];
    __shared__ float Bs[32][68];
    __shared__ float Ts[64][68];
    int b = blockIdx.y;
    int t = blockIdx.x;
    int i = 0;
    while (t >= 32 - i) { t -= 32 - i; i++; }
    int j = i + t;
    int ibase = i * 64, jbase = j * 64;
    const float* xb = x + (size_t)b * CC * NP;
    int tid = threadIdx.x;
    float acc[4][4] = {};
    int to = (tid >> 4) * 4, tn = (tid & 15) * 4;

    for (int kb = 0; kb < CC; kb += 32) {
#pragma unroll
        for (int ii = 0; ii < 2; ii++) {
            int g = tid + ii * 256;
            int n4 = g & 15, kk = g >> 4;
            const float* src = xb + (size_t)(kb + kk) * NP;
            *(float4*)&As[kk][n4 * 4] = *(const float4*)(src + ibase + n4 * 4);
            *(float4*)&Bs[kk][n4 * 4] = *(const float4*)(src + jbase + n4 * 4);
        }
        __syncthreads();
#pragma unroll
        for (int k = 0; k < 32; k++) {
            float4 a = *(const float4*)&As[k][to];
            float4 v = *(const float4*)&Bs[k][tn];
            acc[0][0] = fmaf(a.x, v.x, acc[0][0]); acc[0][1] = fmaf(a.x, v.y, acc[0][1]);
            acc[0][2] = fmaf(a.x, v.z, acc[0][2]); acc[0][3] = fmaf(a.x, v.w, acc[0][3]);
            acc[1][0] = fmaf(a.y, v.x, acc[1][0]); acc[1][1] = fmaf(a.y, v.y, acc[1][1]);
            acc[1][2] = fmaf(a.y, v.z, acc[1][2]); acc[1][3] = fmaf(a.y, v.w, acc[1][3]);
            acc[2][0] = fmaf(a.z, v.x, acc[2][0]); acc[2][1] = fmaf(a.z, v.y, acc[2][1]);
            acc[2][2] = fmaf(a.z, v.z, acc[2][2]); acc[2][3] = fmaf(a.z, v.w, acc[2][3]);
            acc[3][0] = fmaf(a.w, v.x, acc[3][0]); acc[3][1] = fmaf(a.w, v.y, acc[3][1]);
            acc[3][2] = fmaf(a.w, v.z, acc[3][2]); acc[3][3] = fmaf(a.w, v.w, acc[3][3]);
        }
        __syncthreads();
    }
    float xxn[4], xxm[4];
#pragma unroll
    for (int ii = 0; ii < 4; ii++) xxn[ii] = g_buf[O_XX + b * NP + ibase + to + ii];
#pragma unroll
    for (int jj = 0; jj < 4; jj++) xxm[jj] = g_buf[O_XX + b * NP + jbase + tn + jj];

    float* pd = g_buf + O_PD + (size_t)b * NP * NP;
#pragma unroll
    for (int ii = 0; ii < 4; ii++)
#pragma unroll
        for (int jj = 0; jj < 4; jj++) {
            float v = 2.f * acc[ii][jj] - xxn[ii] - xxm[jj];
            pd[(size_t)(ibase + to + ii) * NP + jbase + tn + jj] = v;
            Ts[tn + jj][to + ii] = v;
        }
    if (ibase != jbase) {
        __syncthreads();
#pragma unroll
        for (int tt = 0; tt < 16; tt++) {
            int g = tid + tt * 256;
            int r = g >> 6, cix = g & 63;
            pd[(size_t)(jbase + r) * NP + ibase + cix] = Ts[r][cix];
        }
    }
}

// ---------------- per-row top-20 (set semantics, ties -> lowest index) ----------------
__global__ void topk_kernel() {
    __shared__ float vals[NP];
    __shared__ float rv[8];
    __shared__ int ri[8];
    int row = blockIdx.x;                   // 0 .. B*N-1
    const float* pdrow = g_buf + O_PD + (size_t)row * NP;
    int* idxout = reinterpret_cast<int*>(g_buf + O_IDX) + row * KNN;
    int tid = threadIdx.x;
    for (int i = tid; i < NP; i += 256) vals[i] = pdrow[i];
    __syncthreads();
    for (int it = 0; it < KNN; it++) {
        float bv = -3.4e38f; int bi = NP;
        for (int i = tid; i < NP; i += 256) {
            float v = vals[i];
            if (v > bv) { bv = v; bi = i; }   // ascending scan keeps lowest index on ties
        }
#pragma unroll
        for (int off = 16; off; off >>= 1) {
            float ov = __shfl_down_sync(0xffffffffu, bv, off);
            int oi = __shfl_down_sync(0xffffffffu, bi, off);
            if (ov > bv || (ov == bv && oi < bi)) { bv = ov; bi = oi; }
        }
        if ((tid & 31) == 0) { rv[tid >> 5] = bv; ri[tid >> 5] = bi; }
        __syncthreads();
        if (tid == 0) {
            for (int w = 1; w < 8; w++)
                if (rv[w] > bv || (rv[w] == bv && ri[w] < bi)) { bv = rv[w]; bi = ri[w]; }
            idxout[it] = bi;
            vals[bi] = -3.4e38f;
        }
        __syncthreads();
    }
}

// ---------------- sparse mutual-kNN attention: one warp per (b,n) ----------------
__global__ void attn_kernel() {
    const unsigned FULL = 0xffffffffu;
    int gwarp = (blockIdx.x * blockDim.x + threadIdx.x) >> 5;
    int lane = threadIdx.x & 31;
    int b = gwarp / NP, n = gwarp - b * NP;

    const float* qT = g_buf + O_QT;
    const float* kT = g_buf + O_KT;
    const float* vT = g_buf + O_VT;
    const int* idx = reinterpret_cast<const int*>(g_buf + O_IDX);

    const float* qrow = qT + ((size_t)b * NP + n) * CC;
    float q0 = qrow[lane], q1 = qrow[lane + 32], q2 = qrow[lane + 64], q3 = qrow[lane + 96];

    int mj = 0, act = 0;
    if (lane < KNN) {
        mj = idx[(b * NP + n) * KNN + lane];
        const int* lst = idx + (size_t)(b * NP + mj) * KNN;
#pragma unroll
        for (int tt = 0; tt < KNN; tt++) act |= (lst[tt] == n);
    }
    unsigned amask = __ballot_sync(FULL, act);

    float sc[4] = {0.f, 0.f, 0.f, 0.f};
    for (int jj = 0; jj < KNN; jj++) {
        if (!((amask >> jj) & 1)) continue;
        int m = __shfl_sync(FULL, mj, jj);
        const float* krow = kT + ((size_t)b * NP + m) * CC;
        float p0 = q0 * krow[lane], p1 = q1 * krow[lane + 32];
        float p2 = q2 * krow[lane + 64], p3 = q3 * krow[lane + 96];
#pragma unroll
        for (int off = 16; off; off >>= 1) {
            p0 += __shfl_xor_sync(FULL, p0, off);
            p1 += __shfl_xor_sync(FULL, p1, off);
            p2 += __shfl_xor_sync(FULL, p2, off);
            p3 += __shfl_xor_sync(FULL, p3, off);
        }
        if (lane == jj) { sc[0] = p0; sc[1] = p1; sc[2] = p2; sc[3] = p3; }
    }

    const float scale = 0.17677669529663687f;    // 1/sqrt(32)
    bool live = (lane < KNN) && ((amask >> lane) & 1);
    float p[4];
#pragma unroll
    for (int h = 0; h < 4; h++) {
        float v = live ? sc[h] * scale : -3.4e38f;
        float mx = v;
#pragma unroll
        for (int off = 16; off; off >>= 1) mx = fmaxf(mx, __shfl_xor_sync(FULL, mx, off));
        float e = live ? expf(v - mx) : 0.f;
        float s = e;
#pragma unroll
        for (int off = 16; off; off >>= 1) s += __shfl_xor_sync(FULL, s, off);
        p[h] = e / s;
    }

    float a0 = 0.f, a1 = 0.f, a2 = 0.f, a3 = 0.f;
    for (int jj = 0; jj < KNN; jj++) {
        if (!((amask >> jj) & 1)) continue;
        int m = __shfl_sync(FULL, mj, jj);
        float w0 = __shfl_sync(FULL, p[0], jj);
        float w1 = __shfl_sync(FULL, p[1], jj);
        float w2 = __shfl_sync(FULL, p[2], jj);
        float w3 = __shfl_sync(FULL, p[3], jj);
        const float* vrow = vT + ((size_t)b * NP + m) * CC;
        a0 = fmaf(w0, vrow[lane], a0);
        a1 = fmaf(w1, vrow[lane + 32], a1);
        a2 = fmaf(w2, vrow[lane + 64], a2);
        a3 = fmaf(w3, vrow[lane + 96], a3);
    }
    float* avb = g_buf + O_AV + (size_t)b * CC * NP;
    avb[(size_t)(0 * 32 + lane) * NP + n] = a0;
    avb[(size_t)(1 * 32 + lane) * NP + n] = a1;
    avb[(size_t)(2 * 32 + lane) * NP + n] = a2;
    avb[(size_t)(3 * 32 + lane) * NP + n] = a3;
}

// ---------------- copy x into lower half of concat buffer ----------------
__global__ void copy_x_kernel(const float* __restrict__ x) {
    int i = blockIdx.x * 256 + threadIdx.x;
    if (i >= BB * CC * NP) return;
    int b = i / (CC * NP);
    int r = i - b * CC * NP;
    g_buf[O_CAT + (size_t)b * C2 * NP + r] = x[i];
}

// ---------------- batchnorm statistics over (B, N) per channel ----------------
__global__ void bn_stats_kernel() {
    __shared__ float ss[256], ss2[256];
    int c = blockIdx.x, tid = threadIdx.x;
    float s = 0.f, s2 = 0.f;
    for (int bn = tid; bn < BB * NP; bn += 256) {
        int b = bn >> 11, n = bn & (NP - 1);
        float v = g_buf[O_H + (size_t)b * C2 * NP + (size_t)c * NP + n];
        s += v; s2 = fmaf(v, v, s2);
    }
    ss[tid] = s; ss2[tid] = s2;
    __syncthreads();
    for (int off = 128; off; off >>= 1) {
        if (tid < off) { ss[tid] += ss[tid + off]; ss2[tid] += ss2[tid + off]; }
        __syncthreads();
    }
    if (tid == 0) {
        float inv = 1.f / (BB * NP);
        float mu = ss[0] * inv;
        float var = ss2[0] * inv - mu * mu;
        g_buf[O_MU + c] = mu;
        g_buf[O_ISTD + c] = rsqrtf(var + 1e-5f);
    }
}

// ---------------- launch ----------------
extern "C" void kernel_launch(void* const* d_in, const int* in_sizes, int n_in,
                              void* d_out, int out_size) {
    (void)in_sizes; (void)n_in; (void)out_size;
    const float* x     = (const float*)d_in[0];
    const float* wq    = (const float*)d_in[1];
    const float* bq    = (const float*)d_in[2];
    const float* wk    = (const float*)d_in[3];
    const float* bk    = (const float*)d_in[4];
    const float* wv    = (const float*)d_in[5];
    const float* bv    = (const float*)d_in[6];
    const float* wm    = (const float*)d_in[7];
    const float* bm    = (const float*)d_in[8];
    const float* w1    = (const float*)d_in[9];
    const float* b1    = (const float*)d_in[10];
    const float* gamma = (const float*)d_in[11];
    const float* beta  = (const float*)d_in[12];
    const float* w2    = (const float*)d_in[13];
    const float* b2    = (const float*)d_in[14];
    float* out = (float*)d_out;

    float* base = nullptr;
    cudaGetSymbolAddress((void**)&base, g_buf);
    float* p_qT  = base + O_QT;
    float* p_kT  = base + O_KT;
    float* p_vT  = base + O_VT;
    float* p_av  = base + O_AV;
    float* p_cat = base + O_CAT;
    float* p_h   = base + O_H;

    xx_kernel<<<(BB * NP + 255) / 256, 256>>>(x);

    dim3 g128(NP / 64, CC / 64, BB);
    gemm_conv<CC, true, false, false><<<g128, 256>>>(wq, bq, x, p_qT, CC, 0, 0, nullptr, nullptr, nullptr);
    gemm_conv<CC, true, false, false><<<g128, 256>>>(wk, bk, x, p_kT, CC, 0, 0, nullptr, nullptr, nullptr);
    gemm_conv<CC, true, false, false><<<g128, 256>>>(wv, bv, x, p_vT, CC, 0, 0, nullptr, nullptr, nullptr);

    pd_kernel<<<dim3(528, BB), 256>>>(x);
    topk_kernel<<<BB * NP, 256>>>();
    attn_kernel<<<BB * NP / 8, 256>>>();

    copy_x_kernel<<<(BB * CC * NP + 255) / 256, 256>>>(x);
    // wm conv writes into upper half (rows 128..255) of concat buffer
    gemm_conv<CC, false, false, false><<<g128, 256>>>(wm, bm, p_av, p_cat, CC, C2 * NP, CC, nullptr, nullptr, nullptr);

    dim3 g256(NP / 64, C2 / 64, BB);
    gemm_conv<C2, false, false, false><<<g256, 256>>>(w1, b1, p_cat, p_h, C2, C2 * NP, 0, nullptr, nullptr, nullptr);

    bn_stats_kernel<<<C2, 256>>>();

    // final: out = x + w2 @ relu(bn(h))  — bn+relu fused into X loader, residual in epilogue
    gemm_conv<C2, false, true, true><<<g128, 256>>>(w2, b2, p_h, out, CC, CC * NP, 0, x, gamma, beta);
}

// round 4
// speedup vs baseline: 1.1688x; 1.1688x over previous
#include <cuda_runtime.h>
#include <cuda_fp16.h>
#include <math.h>
#include <stdint.h>

#define BB 2
#define CC 128
#define NP 2048
#define HH 4
#define DD 32
#define KNN 20
#define C2 256

// ---------------- scratch arena ----------------
#define O_QT   0                              // B*N*C  (q transposed [b][n][c])
#define O_KT   (O_QT + BB*NP*CC)
#define O_VT   (O_KT + BB*NP*CC)
#define O_XX   (O_VT + BB*NP*CC)              // B*N
#define O_AV   (O_XX + BB*NP)                 // B*C*N
#define O_AV2  (O_AV + BB*CC*NP)              // B*C*N  (wm output)
#define O_H    (O_AV2 + BB*CC*NP)             // B*2C*N
#define O_MU   (O_H + BB*C2*NP)               // 2C
#define O_ISTD (O_MU + C2)
#define O_IDX  (O_ISTD + C2)                  // B*N*KNN ints
#define O_XH   (O_IDX + BB*NP*KNN)            // B*N*C halfs -> /2 floats
#define O_XM   (O_XH + BB*NP*CC/2)
#define O_PD   (O_XM + BB*NP*CC/2)            // B*N*N
#define TOTALF (O_PD + (size_t)BB*NP*NP)

__device__ float g_buf[TOTALF];

__device__ __forceinline__ uint32_t smem_u32(const void* p) {
    uint32_t a;
    asm("{ .reg .u64 t; cvta.to.shared.u64 t, %1; cvt.u32.u64 %0, t; }" : "=r"(a) : "l"(p));
    return a;
}

// ---------------- xx[b][n] = sum_c x^2 ----------------
__global__ void xx_kernel(const float* __restrict__ x) {
    int i = blockIdx.x * blockDim.x + threadIdx.x;
    if (i >= BB * NP) return;
    int b = i / NP, n = i - b * NP;
    const float* xb = x + (size_t)b * CC * NP + n;
    float s = 0.f;
#pragma unroll 8
    for (int c = 0; c < CC; c++) { float v = xb[(size_t)c * NP]; s = fmaf(v, v, s); }
    g_buf[O_XX + i] = s;
}

// ---------------- transpose + 2-way fp16 split: xT_{h,m}[b][n][c] ----------------
__global__ void prep_kernel(const float* __restrict__ x) {
    __shared__ float ts[32][65];
    int b = blockIdx.z;
    int cbase = blockIdx.y * 32, nbase = blockIdx.x * 64;
    int tid = threadIdx.x;
    __half* xh = reinterpret_cast<__half*>(g_buf + O_XH);
    __half* xm = reinterpret_cast<__half*>(g_buf + O_XM);
#pragma unroll
    for (int i = 0; i < 8; i++) {
        int idx = tid + i * 256;
        int cr = idx >> 6, nn = idx & 63;
        ts[cr][nn] = x[(size_t)b * CC * NP + (size_t)(cbase + cr) * NP + nbase + nn];
    }
    __syncthreads();
#pragma unroll
    for (int i = 0; i < 8; i++) {
        int idx = tid + i * 256;
        int nr = idx >> 5, cc = idx & 31;
        float v = ts[cc][nr];
        __half h1 = __float2half_rn(v);
        float r1 = v - __half2float(h1);
        __half h2 = __float2half_rn(r1);
        size_t o = ((size_t)b * NP + nbase + nr) * CC + cbase + cc;
        xh[o] = h1; xm[o] = h2;
    }
}

// ---------------- pd via mma.sync HMMA: D = (h+m)(h+m)^T, K=512 pattern ----------------
#define LDA 264   // halfs per smem row: 256 data + 8 pad
#define PD_SMEM (1024 + 2 * 128 * LDA * 2)

__global__ void __launch_bounds__(256, 1) pd_mma_kernel() {
    extern __shared__ char ps[];
    float* xxi_s = (float*)ps;              // 128 floats
    float* xxj_s = (float*)(ps + 512);      // 128 floats
    __half* As = (__half*)(ps + 1024);
    __half* Bs = As + 128 * LDA;

    int tid = threadIdx.x, lane = tid & 31, wid = tid >> 5;
    int b = blockIdx.y;
    int t = blockIdx.x;
    int i = 0;
    while (t >= 16 - i) { t -= 16 - i; i++; }
    int j = i + t;
    int ibase = i * 128, jbase = j * 128;

    const __half* xh = reinterpret_cast<const __half*>(g_buf + O_XH);
    const __half* xm = reinterpret_cast<const __half*>(g_buf + O_XM);

    // load A (rows ibase..) and B (rows jbase..): h in cols 0-127, m in cols 128-255
    {
        const __half* srcs[4] = { xh + ((size_t)b * NP + ibase) * CC,
                                  xm + ((size_t)b * NP + ibase) * CC,
                                  xh + ((size_t)b * NP + jbase) * CC,
                                  xm + ((size_t)b * NP + jbase) * CC };
        __half* dsts[4] = { As, As + 128, Bs, Bs + 128 };
#pragma unroll
        for (int s = 0; s < 4; s++) {
            const __half* src = srcs[s];
            __half* dst = dsts[s];
#pragma unroll
            for (int idx = tid; idx < 2048; idx += 256) {
                int row = idx >> 4, ch = idx & 15;
                *(uint4*)(dst + (size_t)row * LDA + ch * 8) =
                    *(const uint4*)(src + (size_t)row * CC + ch * 8);
            }
        }
    }
    if (tid < 128) xxi_s[tid] = g_buf[O_XX + b * NP + ibase + tid];
    else           xxj_s[tid - 128] = g_buf[O_XX + b * NP + jbase + (tid - 128)];
    __syncthreads();

    int mw = wid & 1, nw = wid >> 1;           // 2 m-warps x 4 n-warps
    const __half* Abase = As + (size_t)(mw * 64) * LDA;
    const __half* Bbase = Bs + (size_t)(nw * 32) * LDA;
    uint32_t a_s0 = smem_u32(Abase);
    uint32_t b_s0 = smem_u32(Bbase);

    float acc[4][4][4];
#pragma unroll
    for (int a1 = 0; a1 < 4; a1++)
#pragma unroll
        for (int a2 = 0; a2 < 4; a2++)
#pragma unroll
            for (int a3 = 0; a3 < 4; a3++) acc[a1][a2][a3] = 0.f;

    int lrow = lane & 15, lcol8 = (lane >> 4) * 8;
    const int ACOL[4] = {0, 0, 128, 128};
    const int BCOL[4] = {0, 128, 0, 128};

#pragma unroll
    for (int seg = 0; seg < 4; seg++) {
#pragma unroll
        for (int k16 = 0; k16 < 8; k16++) {
            int akc = ACOL[seg] + k16 * 16 + lcol8;
            int bkc = BCOL[seg] + k16 * 16 + lcol8;
            uint32_t arg[4][4];
#pragma unroll
            for (int mi = 0; mi < 4; mi++) {
                uint32_t addr = a_s0 + (uint32_t)(((mi * 16 + lrow) * LDA + akc) * 2);
                asm volatile("ldmatrix.sync.aligned.m8n8.x4.shared.b16 {%0,%1,%2,%3}, [%4];"
                             : "=r"(arg[mi][0]), "=r"(arg[mi][1]), "=r"(arg[mi][2]), "=r"(arg[mi][3])
                             : "r"(addr));
            }
            uint32_t brg[2][4];
#pragma unroll
            for (int nh = 0; nh < 2; nh++) {
                uint32_t addr = b_s0 + (uint32_t)(((nh * 16 + lrow) * LDA + bkc) * 2);
                asm volatile("ldmatrix.sync.aligned.m8n8.x4.shared.b16 {%0,%1,%2,%3}, [%4];"
                             : "=r"(brg[nh][0]), "=r"(brg[nh][1]), "=r"(brg[nh][2]), "=r"(brg[nh][3])
                             : "r"(addr));
            }
#pragma unroll
            for (int mi = 0; mi < 4; mi++)
#pragma unroll
                for (int ni = 0; ni < 4; ni++) {
                    uint32_t b0 = brg[ni >> 1][ni & 1];
                    uint32_t b1 = brg[ni >> 1][2 + (ni & 1)];
                    asm volatile(
                        "mma.sync.aligned.m16n8k16.row.col.f32.f16.f16.f32 "
                        "{%0,%1,%2,%3}, {%4,%5,%6,%7}, {%8,%9}, {%0,%1,%2,%3};"
                        : "+f"(acc[mi][ni][0]), "+f"(acc[mi][ni][1]),
                          "+f"(acc[mi][ni][2]), "+f"(acc[mi][ni][3])
                        : "r"(arg[mi][0]), "r"(arg[mi][1]), "r"(arg[mi][2]), "r"(arg[mi][3]),
                          "r"(b0), "r"(b1));
                }
        }
    }

    // ---- direct epilogue: pd[ibase+r][jbase+c] ----
    int g = lane >> 2, q = lane & 3;
    float* pdb = g_buf + O_PD + (size_t)b * NP * NP;
#pragma unroll
    for (int mi = 0; mi < 4; mi++)
#pragma unroll
        for (int ni = 0; ni < 4; ni++) {
            int r0 = mw * 64 + mi * 16 + g;
            int c0 = nw * 32 + ni * 8 + q * 2;
            float xj0 = xxj_s[c0], xj1 = xxj_s[c0 + 1];
            float xi0 = xxi_s[r0], xi1 = xxi_s[r0 + 8];
            float2 v01, v23;
            v01.x = 2.f * acc[mi][ni][0] - xi0 - xj0;
            v01.y = 2.f * acc[mi][ni][1] - xi0 - xj1;
            v23.x = 2.f * acc[mi][ni][2] - xi1 - xj0;
            v23.y = 2.f * acc[mi][ni][3] - xi1 - xj1;
            *(float2*)(pdb + (size_t)(ibase + r0) * NP + jbase + c0) = v01;
            *(float2*)(pdb + (size_t)(ibase + r0 + 8) * NP + jbase + c0) = v23;
        }

    // ---- mirrored epilogue via smem transpose (skip on diagonal) ----
    __syncthreads();   // all warps done with ldmatrix reads of As/Bs
    if (ibase != jbase) {
        float* patch = (float*)(ps + 1024) + (size_t)wid * 32 * 68;
#pragma unroll
        for (int mi = 0; mi < 4; mi++)
#pragma unroll
            for (int ni = 0; ni < 4; ni++) {
                int rl = mi * 16 + g;              // local row 0..63
                int cl = ni * 8 + q * 2;           // local col 0..31
                int r0 = mw * 64 + rl, c0 = nw * 32 + cl;
                float xj0 = xxj_s[c0], xj1 = xxj_s[c0 + 1];
                float xi0 = xxi_s[r0], xi1 = xxi_s[r0 + 8];
                patch[(cl + 0) * 68 + rl]     = 2.f * acc[mi][ni][0] - xi0 - xj0;
                patch[(cl + 1) * 68 + rl]     = 2.f * acc[mi][ni][1] - xi0 - xj1;
                patch[(cl + 0) * 68 + rl + 8] = 2.f * acc[mi][ni][2] - xi1 - xj0;
                patch[(cl + 1) * 68 + rl + 8] = 2.f * acc[mi][ni][3] - xi1 - xj1;
            }
        __syncwarp();
#pragma unroll
        for (int cc = 0; cc < 32; cc++) {
            float2 val = *(float2*)(patch + cc * 68 + lane * 2);
            *(float2*)(pdb + (size_t)(jbase + nw * 32 + cc) * NP + ibase + mw * 64 + lane * 2) = val;
        }
    }
}

// ---------------- generic conv1x1 GEMM ----------------
template<int CIN, bool TRANS_OUT, bool BN_IN, bool RES, bool SPLIT>
__global__ void gemm_conv(const float* __restrict__ W, const float* __restrict__ bias,
                          const float* __restrict__ X, const float* __restrict__ X2,
                          float* __restrict__ Y,
                          int O, int out_batch_stride, int out_row_off,
                          const float* __restrict__ resid,
                          const float* __restrict__ gamma, const float* __restrict__ beta)
{
    __shared__ float Ws[32][68];
    __shared__ float Xs[32][68];
    int b = blockIdx.z;
    int obase = blockIdx.y * 64, nbase = blockIdx.x * 64;
    int tid = threadIdx.x;
    float acc[4][4] = {};
    int to = (tid >> 4) * 4, tn = (tid & 15) * 4;

    for (int kb = 0; kb < CIN; kb += 32) {
#pragma unroll
        for (int i = 0; i < 2; i++) {
            int g = tid + i * 256;
            int o = g & 63, kq = g >> 6;
            float4 w4 = *(const float4*)(W + (size_t)(obase + o) * CIN + kb + kq * 4);
            Ws[kq * 4 + 0][o] = w4.x; Ws[kq * 4 + 1][o] = w4.y;
            Ws[kq * 4 + 2][o] = w4.z; Ws[kq * 4 + 3][o] = w4.w;
        }
        const float* bsrc;
        if (SPLIT)
            bsrc = (kb < CC) ? X + (size_t)b * CC * NP + (size_t)kb * NP
                             : X2 + (size_t)b * CC * NP + (size_t)(kb - CC) * NP;
        else
            bsrc = X + (size_t)b * CIN * NP + (size_t)kb * NP;
#pragma unroll
        for (int i = 0; i < 2; i++) {
            int g = tid + i * 256;
            int n4 = g & 15, kk = g >> 4;
            int c = kb + kk;
            float4 x4 = *(const float4*)(bsrc + (size_t)kk * NP + nbase + n4 * 4);
            if (BN_IN) {
                float m = g_buf[O_MU + c], is = g_buf[O_ISTD + c];
                float ga = gamma[c], be = beta[c];
                x4.x = fmaxf(fmaf((x4.x - m) * is, ga, be), 0.f);
                x4.y = fmaxf(fmaf((x4.y - m) * is, ga, be), 0.f);
                x4.z = fmaxf(fmaf((x4.z - m) * is, ga, be), 0.f);
                x4.w = fmaxf(fmaf((x4.w - m) * is, ga, be), 0.f);
            }
            *(float4*)&Xs[kk][n4 * 4] = x4;
        }
        __syncthreads();
#pragma unroll
        for (int k = 0; k < 32; k++) {
            float4 a = *(const float4*)&Ws[k][to];
            float4 v = *(const float4*)&Xs[k][tn];
            acc[0][0] = fmaf(a.x, v.x, acc[0][0]); acc[0][1] = fmaf(a.x, v.y, acc[0][1]);
            acc[0][2] = fmaf(a.x, v.z, acc[0][2]); acc[0][3] = fmaf(a.x, v.w, acc[0][3]);
            acc[1][0] = fmaf(a.y, v.x, acc[1][0]); acc[1][1] = fmaf(a.y, v.y, acc[1][1]);
            acc[1][2] = fmaf(a.y, v.z, acc[1][2]); acc[1][3] = fmaf(a.y, v.w, acc[1][3]);
            acc[2][0] = fmaf(a.z, v.x, acc[2][0]); acc[2][1] = fmaf(a.z, v.y, acc[2][1]);
            acc[2][2] = fmaf(a.z, v.z, acc[2][2]); acc[2][3] = fmaf(a.z, v.w, acc[2][3]);
            acc[3][0] = fmaf(a.w, v.x, acc[3][0]); acc[3][1] = fmaf(a.w, v.y, acc[3][1]);
            acc[3][2] = fmaf(a.w, v.z, acc[3][2]); acc[3][3] = fmaf(a.w, v.w, acc[3][3]);
        }
        __syncthreads();
    }
#pragma unroll
    for (int i = 0; i < 4; i++) {
        int o = obase + to + i;
        float bs = bias[o];
#pragma unroll
        for (int j = 0; j < 4; j++) {
            int n = nbase + tn + j;
            float v = acc[i][j] + bs;
            if (RES) v += resid[(size_t)b * CC * NP + (size_t)o * NP + n];
            if (TRANS_OUT)
                Y[((size_t)b * NP + n) * O + o] = v;
            else
                Y[(size_t)b * out_batch_stride + (size_t)(out_row_off + o) * NP + n] = v;
        }
    }
}

// merged q/k/v conv (writes transposed [b][n][c]), grid.z = 3*B
__global__ void qkv_gemm(const float* __restrict__ wq, const float* __restrict__ bq,
                         const float* __restrict__ wk, const float* __restrict__ bk,
                         const float* __restrict__ wv, const float* __restrict__ bv,
                         const float* __restrict__ X)
{
    __shared__ float Ws[32][68];
    __shared__ float Xs[32][68];
    int z = blockIdx.z;
    int b = z % BB, m = z / BB;
    const float* W = (m == 0) ? wq : (m == 1) ? wk : wv;
    const float* bias = (m == 0) ? bq : (m == 1) ? bk : bv;
    float* Y = g_buf + ((m == 0) ? O_QT : (m == 1) ? O_KT : O_VT);
    int obase = blockIdx.y * 64, nbase = blockIdx.x * 64;
    int tid = threadIdx.x;
    const float* Xb = X + (size_t)b * CC * NP;
    float acc[4][4] = {};
    int to = (tid >> 4) * 4, tn = (tid & 15) * 4;

    for (int kb = 0; kb < CC; kb += 32) {
#pragma unroll
        for (int i = 0; i < 2; i++) {
            int g = tid + i * 256;
            int o = g & 63, kq = g >> 6;
            float4 w4 = *(const float4*)(W + (size_t)(obase + o) * CC + kb + kq * 4);
            Ws[kq * 4 + 0][o] = w4.x; Ws[kq * 4 + 1][o] = w4.y;
            Ws[kq * 4 + 2][o] = w4.z; Ws[kq * 4 + 3][o] = w4.w;
        }
#pragma unroll
        for (int i = 0; i < 2; i++) {
            int g = tid + i * 256;
            int n4 = g & 15, kk = g >> 4;
            *(float4*)&Xs[kk][n4 * 4] =
                *(const float4*)(Xb + (size_t)(kb + kk) * NP + nbase + n4 * 4);
        }
        __syncthreads();
#pragma unroll
        for (int k = 0; k < 32; k++) {
            float4 a = *(const float4*)&Ws[k][to];
            float4 v = *(const float4*)&Xs[k][tn];
            acc[0][0] = fmaf(a.x, v.x, acc[0][0]); acc[0][1] = fmaf(a.x, v.y, acc[0][1]);
            acc[0][2] = fmaf(a.x, v.z, acc[0][2]); acc[0][3] = fmaf(a.x, v.w, acc[0][3]);
            acc[1][0] = fmaf(a.y, v.x, acc[1][0]); acc[1][1] = fmaf(a.y, v.y, acc[1][1]);
            acc[1][2] = fmaf(a.y, v.z, acc[1][2]); acc[1][3] = fmaf(a.y, v.w, acc[1][3]);
            acc[2][0] = fmaf(a.z, v.x, acc[2][0]); acc[2][1] = fmaf(a.z, v.y, acc[2][1]);
            acc[2][2] = fmaf(a.z, v.z, acc[2][2]); acc[2][3] = fmaf(a.z, v.w, acc[2][3]);
            acc[3][0] = fmaf(a.w, v.x, acc[3][0]); acc[3][1] = fmaf(a.w, v.y, acc[3][1]);
            acc[3][2] = fmaf(a.w, v.z, acc[3][2]); acc[3][3] = fmaf(a.w, v.w, acc[3][3]);
        }
        __syncthreads();
    }
#pragma unroll
    for (int i = 0; i < 4; i++) {
        int o = obase + to + i;
        float bs = bias[o];
#pragma unroll
        for (int j = 0; j < 4; j++) {
            int n = nbase + tn + j;
            Y[((size_t)b * NP + n) * CC + o] = acc[i][j] + bs;
        }
    }
}

// ---------------- per-row top-20, register-resident ----------------
__global__ void topk_kernel() {
    __shared__ float rv[8];
    __shared__ int ri[8];
    __shared__ int s_win;
    int row = blockIdx.x;
    const float* pdrow = g_buf + O_PD + (size_t)row * NP;
    int* idxout = reinterpret_cast<int*>(g_buf + O_IDX) + row * KNN;
    int tid = threadIdx.x;
    float v[8];
#pragma unroll
    for (int k = 0; k < 8; k++) v[k] = pdrow[tid + (k << 8)];
    for (int it = 0; it < KNN; it++) {
        float bv = v[0]; int bk = 0;
#pragma unroll
        for (int k = 1; k < 8; k++) if (v[k] > bv) { bv = v[k]; bk = k; }
        int bi = tid + (bk << 8);
#pragma unroll
        for (int off = 16; off; off >>= 1) {
            float ov = __shfl_down_sync(0xffffffffu, bv, off);
            int oi = __shfl_down_sync(0xffffffffu, bi, off);
            if (ov > bv || (ov == bv && oi < bi)) { bv = ov; bi = oi; }
        }
        if ((tid & 31) == 0) { rv[tid >> 5] = bv; ri[tid >> 5] = bi; }
        __syncthreads();
        if (tid == 0) {
            for (int w = 1; w < 8; w++)
                if (rv[w] > bv || (rv[w] == bv && ri[w] < bi)) { bv = rv[w]; bi = ri[w]; }
            idxout[it] = bi;
            s_win = bi;
        }
        __syncthreads();
        int w = s_win;
        if ((w & 255) == tid) v[w >> 8] = -3.4e38f;
    }
}

// ---------------- sparse mutual-kNN attention: one warp per (b,n) ----------------
__global__ void attn_kernel() {
    const unsigned FULL = 0xffffffffu;
    int gwarp = (blockIdx.x * blockDim.x + threadIdx.x) >> 5;
    int lane = threadIdx.x & 31;
    int b = gwarp / NP, n = gwarp - b * NP;

    const float* qT = g_buf + O_QT;
    const float* kT = g_buf + O_KT;
    const float* vT = g_buf + O_VT;
    const int* idx = reinterpret_cast<const int*>(g_buf + O_IDX);

    const float* qrow = qT + ((size_t)b * NP + n) * CC;
    float q0 = qrow[lane], q1 = qrow[lane + 32], q2 = qrow[lane + 64], q3 = qrow[lane + 96];

    int mj = 0, act = 0;
    if (lane < KNN) {
        mj = idx[(b * NP + n) * KNN + lane];
        const int* lst = idx + (size_t)(b * NP + mj) * KNN;
#pragma unroll
        for (int tt = 0; tt < KNN; tt++) act |= (lst[tt] == n);
    }
    unsigned amask = __ballot_sync(FULL, act);

    float sc[4] = {0.f, 0.f, 0.f, 0.f};
    for (int jj = 0; jj < KNN; jj++) {
        if (!((amask >> jj) & 1)) continue;
        int m = __shfl_sync(FULL, mj, jj);
        const float* krow = kT + ((size_t)b * NP + m) * CC;
        float p0 = q0 * krow[lane], p1 = q1 * krow[lane + 32];
        float p2 = q2 * krow[lane + 64], p3 = q3 * krow[lane + 96];
#pragma unroll
        for (int off = 16; off; off >>= 1) {
            p0 += __shfl_xor_sync(FULL, p0, off);
            p1 += __shfl_xor_sync(FULL, p1, off);
            p2 += __shfl_xor_sync(FULL, p2, off);
            p3 += __shfl_xor_sync(FULL, p3, off);
        }
        if (lane == jj) { sc[0] = p0; sc[1] = p1; sc[2] = p2; sc[3] = p3; }
    }

    const float scale = 0.17677669529663687f;
    bool live = (lane < KNN) && ((amask >> lane) & 1);
    float p[4];
#pragma unroll
    for (int h = 0; h < 4; h++) {
        float v = live ? sc[h] * scale : -3.4e38f;
        float mx = v;
#pragma unroll
        for (int off = 16; off; off >>= 1) mx = fmaxf(mx, __shfl_xor_sync(FULL, mx, off));
        float e = live ? expf(v - mx) : 0.f;
        float s = e;
#pragma unroll
        for (int off = 16; off; off >>= 1) s += __shfl_xor_sync(FULL, s, off);
        p[h] = e / s;
    }

    float a0 = 0.f, a1 = 0.f, a2 = 0.f, a3 = 0.f;
    for (int jj = 0; jj < KNN; jj++) {
        if (!((amask >> jj) & 1)) continue;
        int m = __shfl_sync(FULL, mj, jj);
        float w0 = __shfl_sync(FULL, p[0], jj);
        float w1 = __shfl_sync(FULL, p[1], jj);
        float w2 = __shfl_sync(FULL, p[2], jj);
        float w3 = __shfl_sync(FULL, p[3], jj);
        const float* vrow = vT + ((size_t)b * NP + m) * CC;
        a0 = fmaf(w0, vrow[lane], a0);
        a1 = fmaf(w1, vrow[lane + 32], a1);
        a2 = fmaf(w2, vrow[lane + 64], a2);
        a3 = fmaf(w3, vrow[lane + 96], a3);
    }
    float* avb = g_buf + O_AV + (size_t)b * CC * NP;
    avb[(size_t)(0 * 32 + lane) * NP + n] = a0;
    avb[(size_t)(1 * 32 + lane) * NP + n] = a1;
    avb[(size_t)(2 * 32 + lane) * NP + n] = a2;
    avb[(size_t)(3 * 32 + lane) * NP + n] = a3;
}

// ---------------- batchnorm statistics over (B, N) per channel ----------------
__global__ void bn_stats_kernel() {
    __shared__ float ss[256], ss2[256];
    int c = blockIdx.x, tid = threadIdx.x;
    float s = 0.f, s2 = 0.f;
    for (int bn = tid; bn < BB * NP; bn += 256) {
        int b = bn >> 11, n = bn & (NP - 1);
        float v = g_buf[O_H + (size_t)b * C2 * NP + (size_t)c * NP + n];
        s += v; s2 = fmaf(v, v, s2);
    }
    ss[tid] = s; ss2[tid] = s2;
    __syncthreads();
    for (int off = 128; off; off >>= 1) {
        if (tid < off) { ss[tid] += ss[tid + off]; ss2[tid] += ss2[tid + off]; }
        __syncthreads();
    }
    if (tid == 0) {
        float inv = 1.f / (BB * NP);
        float mu = ss[0] * inv;
        float var = ss2[0] * inv - mu * mu;
        g_buf[O_MU + c] = mu;
        g_buf[O_ISTD + c] = rsqrtf(var + 1e-5f);
    }
}

// ---------------- launch ----------------
extern "C" void kernel_launch(void* const* d_in, const int* in_sizes, int n_in,
                              void* d_out, int out_size) {
    (void)in_sizes; (void)n_in; (void)out_size;
    const float* x     = (const float*)d_in[0];
    const float* wq    = (const float*)d_in[1];
    const float* bq    = (const float*)d_in[2];
    const float* wk    = (const float*)d_in[3];
    const float* bk    = (const float*)d_in[4];
    const float* wv    = (const float*)d_in[5];
    const float* bv    = (const float*)d_in[6];
    const float* wm    = (const float*)d_in[7];
    const float* bm    = (const float*)d_in[8];
    const float* w1    = (const float*)d_in[9];
    const float* b1    = (const float*)d_in[10];
    const float* gamma = (const float*)d_in[11];
    const float* beta  = (const float*)d_in[12];
    const float* w2    = (const float*)d_in[13];
    const float* b2    = (const float*)d_in[14];
    float* out = (float*)d_out;

    float* base = nullptr;
    cudaGetSymbolAddress((void**)&base, g_buf);
    float* p_av  = base + O_AV;
    float* p_av2 = base + O_AV2;
    float* p_h   = base + O_H;

    cudaFuncSetAttribute(pd_mma_kernel, cudaFuncAttributeMaxDynamicSharedMemorySize, PD_SMEM);

    prep_kernel<<<dim3(NP / 64, CC / 32, BB), 256>>>(x);
    xx_kernel<<<(BB * NP + 255) / 256, 256>>>(x);

    qkv_gemm<<<dim3(NP / 64, CC / 64, 3 * BB), 256>>>(wq, bq, wk, bk, wv, bv, x);

    pd_mma_kernel<<<dim3(136, BB), 256, PD_SMEM>>>();
    topk_kernel<<<BB * NP, 256>>>();
    attn_kernel<<<BB * NP / 8, 256>>>();

    dim3 g128(NP / 64, CC / 64, BB);
    gemm_conv<CC, false, false, false, false><<<g128, 256>>>(
        wm, bm, p_av, nullptr, p_av2, CC, CC * NP, 0, nullptr, nullptr, nullptr);

    dim3 g256(NP / 64, C2 / 64, BB);
    gemm_conv<C2, false, false, false, true><<<g256, 256>>>(
        w1, b1, x, p_av2, p_h, C2, C2 * NP, 0, nullptr, nullptr, nullptr);

    bn_stats_kernel<<<C2, 256>>>();

    gemm_conv<C2, false, true, true, false><<<g128, 256>>>(
        w2, b2, p_h, nullptr, out, CC, CC * NP, 0, x, gamma, beta);
}

// round 5
// speedup vs baseline: 1.5115x; 1.2932x over previous
#include <cuda_runtime.h>
#include <cuda_fp16.h>
#include <math.h>
#include <stdint.h>

#define BB 2
#define CC 128
#define NP 2048
#define KNN 20
#define C2 256

// packed weight-split offsets (halfs)
#define WOFF_Q 0
#define WOFF_K 16384
#define WOFF_V 32768
#define WOFF_M 49152
#define WOFF_1 65536
#define WOFF_2 131072
#define WTOT   163840

// ---------------- scratch arena (floats) ----------------
#define O_QT   0                               // 3 * B*N*C fp32 (q,k,v transposed [b][n][c])
#define O_XX   (O_QT + 3*BB*NP*CC)
#define O_H    (O_XX + BB*NP)                  // B*2C*N fp32 (w1 out, [b][c][n])
#define O_MU   (O_H + BB*C2*NP)
#define O_ISTD (O_MU + C2)
#define O_IDX  (O_ISTD + C2)                   // B*N*KNN ints
#define O_XH   (O_IDX + BB*NP*KNN)             // halfs [b][n][c]
#define O_XM   (O_XH + BB*NP*CC/2)
#define O_AVH  (O_XM + BB*NP*CC/2)
#define O_AVM  (O_AVH + BB*NP*CC/2)
#define O_A2H  (O_AVM + BB*NP*CC/2)
#define O_A2M  (O_A2H + BB*NP*CC/2)
#define O_H2H  (O_A2M + BB*NP*CC/2)            // halfs [b][n][2C]
#define O_H2M  (O_H2H + BB*NP*C2/2)
#define O_WH   (O_H2M + BB*NP*C2/2)            // packed weight halves
#define O_WM2  (O_WH + WTOT/2)
#define O_PD   (O_WM2 + WTOT/2)
#define TOTALF (O_PD + (size_t)BB*NP*NP)

__device__ __align__(16) float g_buf[TOTALF];

__device__ __forceinline__ uint32_t smem_u32(const void* p) {
    uint32_t a;
    asm("{ .reg .u64 t; cvta.to.shared.u64 t, %1; cvt.u32.u64 %0, t; }" : "=r"(a) : "l"(p));
    return a;
}

// ---------------- xx[b][n] = sum_c x^2 ----------------
__global__ void xx_kernel(const float* __restrict__ x) {
    int i = blockIdx.x * blockDim.x + threadIdx.x;
    if (i >= BB * NP) return;
    int b = i / NP, n = i - b * NP;
    const float* xb = x + (size_t)b * CC * NP + n;
    float s = 0.f;
#pragma unroll 8
    for (int c = 0; c < CC; c++) { float v = xb[(size_t)c * NP]; s = fmaf(v, v, s); }
    g_buf[O_XX + i] = s;
}

// ---------------- transpose + 2-way fp16 split: xT_{h,m}[b][n][c] ----------------
__global__ void prep_kernel(const float* __restrict__ x) {
    __shared__ float ts[32][65];
    int b = blockIdx.z;
    int cbase = blockIdx.y * 32, nbase = blockIdx.x * 64;
    int tid = threadIdx.x;
    __half* xh = reinterpret_cast<__half*>(g_buf + O_XH);
    __half* xm = reinterpret_cast<__half*>(g_buf + O_XM);
#pragma unroll
    for (int i = 0; i < 8; i++) {
        int idx = tid + i * 256;
        int cr = idx >> 6, nn = idx & 63;
        ts[cr][nn] = x[(size_t)b * CC * NP + (size_t)(cbase + cr) * NP + nbase + nn];
    }
    __syncthreads();
#pragma unroll
    for (int i = 0; i < 8; i++) {
        int idx = tid + i * 256;
        int nr = idx >> 5, cc = idx & 31;
        float v = ts[cc][nr];
        __half h1 = __float2half_rn(v);
        __half h2 = __float2half_rn(v - __half2float(h1));
        size_t o = ((size_t)b * NP + nbase + nr) * CC + cbase + cc;
        xh[o] = h1; xm[o] = h2;
    }
}

// ---------------- split all weights to fp16 h/m ----------------
__global__ void wsplit_kernel(const float* __restrict__ wq, const float* __restrict__ wk,
                              const float* __restrict__ wv, const float* __restrict__ wmp,
                              const float* __restrict__ w1, const float* __restrict__ w2) {
    int i = blockIdx.x * 256 + threadIdx.x;
    if (i >= WTOT) return;
    float v;
    if (i < 16384) v = wq[i];
    else if (i < 32768) v = wk[i - 16384];
    else if (i < 49152) v = wv[i - 32768];
    else if (i < 65536) v = wmp[i - 49152];
    else if (i < 131072) v = w1[i - 65536];
    else v = w2[i - 131072];
    __half h = __float2half_rn(v);
    reinterpret_cast<__half*>(g_buf + O_WH)[i] = h;
    reinterpret_cast<__half*>(g_buf + O_WM2)[i] = __float2half_rn(v - __half2float(h));
}

// ---------------- pd via mma.sync HMMA: D = (h+m)(h+m)^T, K=512 pattern ----------------
#define LDA 264
#define PD_SMEM (1024 + 2 * 128 * LDA * 2)

__global__ void __launch_bounds__(256, 1) pd_mma_kernel() {
    extern __shared__ char ps[];
    float* xxi_s = (float*)ps;
    float* xxj_s = (float*)(ps + 512);
    __half* As = (__half*)(ps + 1024);
    __half* Bs = As + 128 * LDA;

    int tid = threadIdx.x, lane = tid & 31, wid = tid >> 5;
    int b = blockIdx.y;
    int t = blockIdx.x;
    int i = 0;
    while (t >= 16 - i) { t -= 16 - i; i++; }
    int j = i + t;
    int ibase = i * 128, jbase = j * 128;

    const __half* xh = reinterpret_cast<const __half*>(g_buf + O_XH);
    const __half* xm = reinterpret_cast<const __half*>(g_buf + O_XM);

    {
        const __half* srcs[4] = { xh + ((size_t)b * NP + ibase) * CC,
                                  xm + ((size_t)b * NP + ibase) * CC,
                                  xh + ((size_t)b * NP + jbase) * CC,
                                  xm + ((size_t)b * NP + jbase) * CC };
        __half* dsts[4] = { As, As + 128, Bs, Bs + 128 };
#pragma unroll
        for (int s = 0; s < 4; s++) {
            const __half* src = srcs[s];
            __half* dst = dsts[s];
#pragma unroll
            for (int idx = tid; idx < 2048; idx += 256) {
                int row = idx >> 4, ch = idx & 15;
                *(uint4*)(dst + (size_t)row * LDA + ch * 8) =
                    *(const uint4*)(src + (size_t)row * CC + ch * 8);
            }
        }
    }
    if (tid < 128) xxi_s[tid] = g_buf[O_XX + b * NP + ibase + tid];
    else           xxj_s[tid - 128] = g_buf[O_XX + b * NP + jbase + (tid - 128)];
    __syncthreads();

    int mw = wid & 1, nw = wid >> 1;
    uint32_t a_s0 = smem_u32(As + (size_t)(mw * 64) * LDA);
    uint32_t b_s0 = smem_u32(Bs + (size_t)(nw * 32) * LDA);

    float acc[4][4][4];
#pragma unroll
    for (int a1 = 0; a1 < 4; a1++)
#pragma unroll
        for (int a2 = 0; a2 < 4; a2++)
#pragma unroll
            for (int a3 = 0; a3 < 4; a3++) acc[a1][a2][a3] = 0.f;

    int lrow = lane & 15, lcol8 = (lane >> 4) * 8;
    const int ACOL[4] = {0, 0, 128, 128};
    const int BCOL[4] = {0, 128, 0, 128};

#pragma unroll
    for (int seg = 0; seg < 4; seg++) {
#pragma unroll
        for (int k16 = 0; k16 < 8; k16++) {
            int akc = ACOL[seg] + k16 * 16 + lcol8;
            int bkc = BCOL[seg] + k16 * 16 + lcol8;
            uint32_t arg[4][4];
#pragma unroll
            for (int mi = 0; mi < 4; mi++) {
                uint32_t addr = a_s0 + (uint32_t)(((mi * 16 + lrow) * LDA + akc) * 2);
                asm volatile("ldmatrix.sync.aligned.m8n8.x4.shared.b16 {%0,%1,%2,%3}, [%4];"
                             : "=r"(arg[mi][0]), "=r"(arg[mi][1]), "=r"(arg[mi][2]), "=r"(arg[mi][3])
                             : "r"(addr));
            }
            uint32_t brg[2][4];
#pragma unroll
            for (int nh = 0; nh < 2; nh++) {
                uint32_t addr = b_s0 + (uint32_t)(((nh * 16 + lrow) * LDA + bkc) * 2);
                asm volatile("ldmatrix.sync.aligned.m8n8.x4.shared.b16 {%0,%1,%2,%3}, [%4];"
                             : "=r"(brg[nh][0]), "=r"(brg[nh][1]), "=r"(brg[nh][2]), "=r"(brg[nh][3])
                             : "r"(addr));
            }
#pragma unroll
            for (int mi = 0; mi < 4; mi++)
#pragma unroll
                for (int ni = 0; ni < 4; ni++) {
                    uint32_t b0 = brg[ni >> 1][ni & 1];
                    uint32_t b1 = brg[ni >> 1][2 + (ni & 1)];
                    asm volatile(
                        "mma.sync.aligned.m16n8k16.row.col.f32.f16.f16.f32 "
                        "{%0,%1,%2,%3}, {%4,%5,%6,%7}, {%8,%9}, {%0,%1,%2,%3};"
                        : "+f"(acc[mi][ni][0]), "+f"(acc[mi][ni][1]),
                          "+f"(acc[mi][ni][2]), "+f"(acc[mi][ni][3])
                        : "r"(arg[mi][0]), "r"(arg[mi][1]), "r"(arg[mi][2]), "r"(arg[mi][3]),
                          "r"(b0), "r"(b1));
                }
        }
    }

    int g = lane >> 2, q = lane & 3;
    float* pdb = g_buf + O_PD + (size_t)b * NP * NP;
#pragma unroll
    for (int mi = 0; mi < 4; mi++)
#pragma unroll
        for (int ni = 0; ni < 4; ni++) {
            int r0 = mw * 64 + mi * 16 + g;
            int c0 = nw * 32 + ni * 8 + q * 2;
            float xj0 = xxj_s[c0], xj1 = xxj_s[c0 + 1];
            float xi0 = xxi_s[r0], xi1 = xxi_s[r0 + 8];
            float2 v01, v23;
            v01.x = 2.f * acc[mi][ni][0] - xi0 - xj0;
            v01.y = 2.f * acc[mi][ni][1] - xi0 - xj1;
            v23.x = 2.f * acc[mi][ni][2] - xi1 - xj0;
            v23.y = 2.f * acc[mi][ni][3] - xi1 - xj1;
            *(float2*)(pdb + (size_t)(ibase + r0) * NP + jbase + c0) = v01;
            *(float2*)(pdb + (size_t)(ibase + r0 + 8) * NP + jbase + c0) = v23;
        }

    __syncthreads();
    if (ibase != jbase) {
        float* patch = (float*)(ps + 1024) + (size_t)wid * 32 * 68;
#pragma unroll
        for (int mi = 0; mi < 4; mi++)
#pragma unroll
            for (int ni = 0; ni < 4; ni++) {
                int rl = mi * 16 + g;
                int cl = ni * 8 + q * 2;
                int r0 = mw * 64 + rl, c0 = nw * 32 + cl;
                float xj0 = xxj_s[c0], xj1 = xxj_s[c0 + 1];
                float xi0 = xxi_s[r0], xi1 = xxi_s[r0 + 8];
                patch[(cl + 0) * 68 + rl]     = 2.f * acc[mi][ni][0] - xi0 - xj0;
                patch[(cl + 1) * 68 + rl]     = 2.f * acc[mi][ni][1] - xi0 - xj1;
                patch[(cl + 0) * 68 + rl + 8] = 2.f * acc[mi][ni][2] - xi1 - xj0;
                patch[(cl + 1) * 68 + rl + 8] = 2.f * acc[mi][ni][3] - xi1 - xj1;
            }
        __syncwarp();
#pragma unroll
        for (int cc = 0; cc < 32; cc++) {
            float2 val = *(float2*)(patch + cc * 68 + lane * 2);
            *(float2*)(pdb + (size_t)(jbase + nw * 32 + cc) * NP + ibase + mw * 64 + lane * 2) = val;
        }
    }
}

// ---------------- HMMA conv1x1: out = W(128xK) * X(Nx K)^T, 2-term split, 3 products ----------
// MODE 0=QKV (y=matrix, out fp32 [b][n][c])  1=WM (out half-split [b][n][c])
//      2=W1 (K=256, y=obase/128, out fp32 [b][o][n])  3=W2 (K=256, +bn input, residual, out fp32)
#define CLDA 264
#define CONV_SMEM (2 * 128 * CLDA * 2)

template<int MODE>
__global__ void __launch_bounds__(256, 1) conv_mma(const float* __restrict__ bias0,
                                                   const float* __restrict__ bias1,
                                                   const float* __restrict__ bias2,
                                                   const float* __restrict__ resid,
                                                   float* __restrict__ outp) {
    extern __shared__ char cs[];
    __half* As = (__half*)cs;
    __half* Bs = As + 128 * CLDA;
    int tid = threadIdx.x, lane = tid & 31, wid = tid >> 5;
    int b = blockIdx.z, nbase = blockIdx.x * 128;
    int yb = blockIdx.y;

    const __half* WH = reinterpret_cast<const __half*>(g_buf + O_WH);
    const __half* WM = reinterpret_cast<const __half*>(g_buf + O_WM2);
    int woff, wstride, obase = 0;
    if (MODE == 0)      { woff = yb * 16384; wstride = 128; }
    else if (MODE == 1) { woff = WOFF_M; wstride = 128; }
    else if (MODE == 2) { woff = WOFF_1 + yb * 128 * 256; wstride = 256; obase = yb * 128; }
    else                { woff = WOFF_2; wstride = 256; }
    const int KCH = (MODE >= 2) ? 2 : 1;

    float acc[4][4][4];
#pragma unroll
    for (int a1 = 0; a1 < 4; a1++)
#pragma unroll
        for (int a2 = 0; a2 < 4; a2++)
#pragma unroll
            for (int a3 = 0; a3 < 4; a3++) acc[a1][a2][a3] = 0.f;

    int mw = wid & 1, nw = wid >> 1;
    int lrow = lane & 15, lcol8 = (lane >> 4) * 8;
    uint32_t a_s0 = smem_u32(As + (size_t)(mw * 64) * CLDA);
    uint32_t b_s0 = smem_u32(Bs + (size_t)(nw * 32) * CLDA);

#pragma unroll
    for (int kc = 0; kc < KCH; kc++) {
        const __half* wsh = WH + woff + kc * 128;
        const __half* wsm = WM + woff + kc * 128;
#pragma unroll
        for (int idx = tid; idx < 2048; idx += 256) {
            int row = idx >> 4, ch = idx & 15;
            *(uint4*)(As + (size_t)row * CLDA + ch * 8) =
                *(const uint4*)(wsh + (size_t)row * wstride + ch * 8);
            *(uint4*)(As + (size_t)row * CLDA + 128 + ch * 8) =
                *(const uint4*)(wsm + (size_t)row * wstride + ch * 8);
        }
        const __half *bh, *bm; int bstr;
        if (MODE == 0) { bh = (const __half*)(g_buf + O_XH); bm = (const __half*)(g_buf + O_XM); bstr = 128; }
        else if (MODE == 1) { bh = (const __half*)(g_buf + O_AVH); bm = (const __half*)(g_buf + O_AVM); bstr = 128; }
        else if (MODE == 2) {
            if (kc == 0) { bh = (const __half*)(g_buf + O_XH); bm = (const __half*)(g_buf + O_XM); }
            else         { bh = (const __half*)(g_buf + O_A2H); bm = (const __half*)(g_buf + O_A2M); }
            bstr = 128;
        } else {
            bh = (const __half*)(g_buf + O_H2H) + kc * 128;
            bm = (const __half*)(g_buf + O_H2M) + kc * 128;
            bstr = 256;
        }
        const __half* bhp = bh + (size_t)(b * NP + nbase) * bstr;
        const __half* bmp = bm + (size_t)(b * NP + nbase) * bstr;
#pragma unroll
        for (int idx = tid; idx < 2048; idx += 256) {
            int row = idx >> 4, ch = idx & 15;
            *(uint4*)(Bs + (size_t)row * CLDA + ch * 8) =
                *(const uint4*)(bhp + (size_t)row * bstr + ch * 8);
            *(uint4*)(Bs + (size_t)row * CLDA + 128 + ch * 8) =
                *(const uint4*)(bmp + (size_t)row * bstr + ch * 8);
        }
        __syncthreads();

        const int ACOL[3] = {0, 0, 128};
        const int BCOL[3] = {0, 128, 0};
#pragma unroll
        for (int seg = 0; seg < 3; seg++) {
#pragma unroll
            for (int k16 = 0; k16 < 8; k16++) {
                int akc = ACOL[seg] + k16 * 16 + lcol8;
                int bkc = BCOL[seg] + k16 * 16 + lcol8;
                uint32_t arg[4][4];
#pragma unroll
                for (int mi = 0; mi < 4; mi++) {
                    uint32_t addr = a_s0 + (uint32_t)(((mi * 16 + lrow) * CLDA + akc) * 2);
                    asm volatile("ldmatrix.sync.aligned.m8n8.x4.shared.b16 {%0,%1,%2,%3}, [%4];"
                                 : "=r"(arg[mi][0]), "=r"(arg[mi][1]), "=r"(arg[mi][2]), "=r"(arg[mi][3])
                                 : "r"(addr));
                }
                uint32_t brg[2][4];
#pragma unroll
                for (int nh = 0; nh < 2; nh++) {
                    uint32_t addr = b_s0 + (uint32_t)(((nh * 16 + lrow) * CLDA + bkc) * 2);
                    asm volatile("ldmatrix.sync.aligned.m8n8.x4.shared.b16 {%0,%1,%2,%3}, [%4];"
                                 : "=r"(brg[nh][0]), "=r"(brg[nh][1]), "=r"(brg[nh][2]), "=r"(brg[nh][3])
                                 : "r"(addr));
                }
#pragma unroll
                for (int mi = 0; mi < 4; mi++)
#pragma unroll
                    for (int ni = 0; ni < 4; ni++) {
                        uint32_t b0 = brg[ni >> 1][ni & 1];
                        uint32_t b1 = brg[ni >> 1][2 + (ni & 1)];
                        asm volatile(
                            "mma.sync.aligned.m16n8k16.row.col.f32.f16.f16.f32 "
                            "{%0,%1,%2,%3}, {%4,%5,%6,%7}, {%8,%9}, {%0,%1,%2,%3};"
                            : "+f"(acc[mi][ni][0]), "+f"(acc[mi][ni][1]),
                              "+f"(acc[mi][ni][2]), "+f"(acc[mi][ni][3])
                            : "r"(arg[mi][0]), "r"(arg[mi][1]), "r"(arg[mi][2]), "r"(arg[mi][3]),
                              "r"(b0), "r"(b1));
                    }
            }
        }
        __syncthreads();
    }

    int g = lane >> 2, q = lane & 3;
    if (MODE <= 1) {
        // transposed epilogue via smem patch
        const float* bias_ = (MODE == 0) ? (yb == 0 ? bias0 : yb == 1 ? bias1 : bias2) : bias0;
        float* patch = (float*)cs + (size_t)wid * 32 * 68;
#pragma unroll
        for (int mi = 0; mi < 4; mi++)
#pragma unroll
            for (int ni = 0; ni < 4; ni++) {
                int rl = mi * 16 + g;
                int cl = ni * 8 + q * 2;
                float bs0 = bias_[mw * 64 + rl], bs1 = bias_[mw * 64 + rl + 8];
                patch[(cl + 0) * 68 + rl]     = acc[mi][ni][0] + bs0;
                patch[(cl + 1) * 68 + rl]     = acc[mi][ni][1] + bs0;
                patch[(cl + 0) * 68 + rl + 8] = acc[mi][ni][2] + bs1;
                patch[(cl + 1) * 68 + rl + 8] = acc[mi][ni][3] + bs1;
            }
        __syncwarp();
        if (MODE == 0) {
            float* Y = g_buf + O_QT + (size_t)yb * BB * NP * CC;
#pragma unroll
            for (int r = 0; r < 32; r++) {
                int n = nbase + nw * 32 + r;
                *(float2*)(Y + ((size_t)b * NP + n) * CC + mw * 64 + lane * 2) =
                    *(float2*)(patch + r * 68 + lane * 2);
            }
        } else {
            __half* Yh = (__half*)(g_buf + O_A2H);
            __half* Ym = (__half*)(g_buf + O_A2M);
#pragma unroll
            for (int r = 0; r < 32; r++) {
                int n = nbase + nw * 32 + r;
                float2 v = *(float2*)(patch + r * 68 + lane * 2);
                __half h0 = __float2half_rn(v.x), h1 = __float2half_rn(v.y);
                __half m0 = __float2half_rn(v.x - __half2float(h0));
                __half m1 = __float2half_rn(v.y - __half2float(h1));
                size_t o = ((size_t)b * NP + n) * CC + mw * 64 + lane * 2;
                *(__half2*)(Yh + o) = __halves2half2(h0, h1);
                *(__half2*)(Ym + o) = __halves2half2(m0, m1);
            }
        }
    } else {
        const float* bias_ = bias0;
        float* Yb = outp + (size_t)b * ((MODE == 2) ? C2 * NP : CC * NP);
#pragma unroll
        for (int mi = 0; mi < 4; mi++)
#pragma unroll
            for (int ni = 0; ni < 4; ni++) {
                int r0 = obase + mw * 64 + mi * 16 + g;
                int c0 = nbase + nw * 32 + ni * 8 + q * 2;
                float bs0 = bias_[r0], bs1 = bias_[r0 + 8];
                float2 v01, v23;
                v01.x = acc[mi][ni][0] + bs0; v01.y = acc[mi][ni][1] + bs0;
                v23.x = acc[mi][ni][2] + bs1; v23.y = acc[mi][ni][3] + bs1;
                if (MODE == 3) {
                    const float* rb = resid + (size_t)b * CC * NP;
                    v01.x += rb[(size_t)r0 * NP + c0];
                    v01.y += rb[(size_t)r0 * NP + c0 + 1];
                    v23.x += rb[(size_t)(r0 + 8) * NP + c0];
                    v23.y += rb[(size_t)(r0 + 8) * NP + c0 + 1];
                }
                *(float2*)(Yb + (size_t)r0 * NP + c0) = v01;
                *(float2*)(Yb + (size_t)(r0 + 8) * NP + c0) = v23;
            }
    }
}

// ---------------- warp-per-row top-20 ----------------
#define TOPK_SMEM (8 * 2048 * 4)
__global__ void __launch_bounds__(256) topk_kernel() {
    extern __shared__ float srows[];
    const unsigned FULL = 0xffffffffu;
    int tid = threadIdx.x, lane = tid & 31, wid = tid >> 5;
    int rowbase = blockIdx.x * 8;
    const float4* g4 = (const float4*)(g_buf + O_PD + (size_t)rowbase * NP);
    float4* s4 = (float4*)srows;
#pragma unroll
    for (int i = tid; i < 8 * 512; i += 256) s4[i] = g4[i];
    __syncthreads();

    float* s = srows + wid * 2048 + lane * 64;
    float bv = -3.4e38f; int bi = 0;
#pragma unroll
    for (int k4 = 0; k4 < 16; k4++) {
        float4 vv = *(float4*)(s + k4 * 4);
        if (vv.x > bv) { bv = vv.x; bi = k4 * 4 + 0; }
        if (vv.y > bv) { bv = vv.y; bi = k4 * 4 + 1; }
        if (vv.z > bv) { bv = vv.z; bi = k4 * 4 + 2; }
        if (vv.w > bv) { bv = vv.w; bi = k4 * 4 + 3; }
    }
    int gbase = lane * 64;
    int* idxout = reinterpret_cast<int*>(g_buf + O_IDX) + (size_t)(rowbase + wid) * KNN;

    for (int it = 0; it < KNN; it++) {
        float cv = bv; int ci = gbase + bi;
#pragma unroll
        for (int off = 16; off; off >>= 1) {
            float ov = __shfl_down_sync(FULL, cv, off);
            int oi = __shfl_down_sync(FULL, ci, off);
            if (ov > cv || (ov == cv && oi < ci)) { cv = ov; ci = oi; }
        }
        ci = __shfl_sync(FULL, ci, 0);
        if (lane == 0) idxout[it] = ci;
        if ((ci >> 6) == lane) {
            s[ci & 63] = -3.4e38f;
            bv = -3.4e38f; bi = 0;
#pragma unroll
            for (int k4 = 0; k4 < 16; k4++) {
                float4 vv = *(float4*)(s + k4 * 4);
                if (vv.x > bv) { bv = vv.x; bi = k4 * 4 + 0; }
                if (vv.y > bv) { bv = vv.y; bi = k4 * 4 + 1; }
                if (vv.z > bv) { bv = vv.z; bi = k4 * 4 + 2; }
                if (vv.w > bv) { bv = vv.w; bi = k4 * 4 + 3; }
            }
        }
    }
}

// ---------------- sparse mutual-kNN attention: one warp per (b,n) ----------------
__global__ void attn_kernel() {
    const unsigned FULL = 0xffffffffu;
    int gwarp = (blockIdx.x * blockDim.x + threadIdx.x) >> 5;
    int lane = threadIdx.x & 31;
    int b = gwarp / NP, n = gwarp - b * NP;

    const float* qT = g_buf + O_QT;
    const float* kT = g_buf + O_QT + BB * NP * CC;
    const float* vT = g_buf + O_QT + 2 * BB * NP * CC;
    const int* idx = reinterpret_cast<const int*>(g_buf + O_IDX);

    const float* qrow = qT + ((size_t)b * NP + n) * CC;
    float q0 = qrow[lane], q1 = qrow[lane + 32], q2 = qrow[lane + 64], q3 = qrow[lane + 96];

    int mj = 0, act = 0;
    if (lane < KNN) {
        mj = idx[(b * NP + n) * KNN + lane];
        const int* lst = idx + (size_t)(b * NP + mj) * KNN;
#pragma unroll
        for (int tt = 0; tt < KNN; tt++) act |= (lst[tt] == n);
    }
    unsigned amask = __ballot_sync(FULL, act);

    float sc[4] = {0.f, 0.f, 0.f, 0.f};
    for (int jj = 0; jj < KNN; jj++) {
        if (!((amask >> jj) & 1)) continue;
        int m = __shfl_sync(FULL, mj, jj);
        const float* krow = kT + ((size_t)b * NP + m) * CC;
        float p0 = q0 * krow[lane], p1 = q1 * krow[lane + 32];
        float p2 = q2 * krow[lane + 64], p3 = q3 * krow[lane + 96];
#pragma unroll
        for (int off = 16; off; off >>= 1) {
            p0 += __shfl_xor_sync(FULL, p0, off);
            p1 += __shfl_xor_sync(FULL, p1, off);
            p2 += __shfl_xor_sync(FULL, p2, off);
            p3 += __shfl_xor_sync(FULL, p3, off);
        }
        if (lane == jj) { sc[0] = p0; sc[1] = p1; sc[2] = p2; sc[3] = p3; }
    }

    const float scale = 0.17677669529663687f;
    bool live = (lane < KNN) && ((amask >> lane) & 1);
    float p[4];
#pragma unroll
    for (int hh = 0; hh < 4; hh++) {
        float v = live ? sc[hh] * scale : -3.4e38f;
        float mx = v;
#pragma unroll
        for (int off = 16; off; off >>= 1) mx = fmaxf(mx, __shfl_xor_sync(FULL, mx, off));
        float e = live ? expf(v - mx) : 0.f;
        float sm = e;
#pragma unroll
        for (int off = 16; off; off >>= 1) sm += __shfl_xor_sync(FULL, sm, off);
        p[hh] = e / sm;
    }

    float a0 = 0.f, a1 = 0.f, a2 = 0.f, a3 = 0.f;
    for (int jj = 0; jj < KNN; jj++) {
        if (!((amask >> jj) & 1)) continue;
        int m = __shfl_sync(FULL, mj, jj);
        float w0 = __shfl_sync(FULL, p[0], jj);
        float w1 = __shfl_sync(FULL, p[1], jj);
        float w2 = __shfl_sync(FULL, p[2], jj);
        float w3 = __shfl_sync(FULL, p[3], jj);
        const float* vrow = vT + ((size_t)b * NP + m) * CC;
        a0 = fmaf(w0, vrow[lane], a0);
        a1 = fmaf(w1, vrow[lane + 32], a1);
        a2 = fmaf(w2, vrow[lane + 64], a2);
        a3 = fmaf(w3, vrow[lane + 96], a3);
    }
    __half* avh = (__half*)(g_buf + O_AVH);
    __half* avm = (__half*)(g_buf + O_AVM);
    size_t o = ((size_t)b * NP + n) * CC;
    float vals[4] = {a0, a1, a2, a3};
#pragma unroll
    for (int c = 0; c < 4; c++) {
        __half hh = __float2half_rn(vals[c]);
        avh[o + c * 32 + lane] = hh;
        avm[o + c * 32 + lane] = __float2half_rn(vals[c] - __half2float(hh));
    }
}

// ---------------- batchnorm statistics ----------------
__global__ void bn_stats_kernel() {
    __shared__ float ss[256], ss2[256];
    int c = blockIdx.x, tid = threadIdx.x;
    float s = 0.f, s2 = 0.f;
    for (int bn = tid; bn < BB * NP; bn += 256) {
        int b = bn >> 11, n = bn & (NP - 1);
        float v = g_buf[O_H + (size_t)b * C2 * NP + (size_t)c * NP + n];
        s += v; s2 = fmaf(v, v, s2);
    }
    ss[tid] = s; ss2[tid] = s2;
    __syncthreads();
    for (int off = 128; off; off >>= 1) {
        if (tid < off) { ss[tid] += ss[tid + off]; ss2[tid] += ss2[tid + off]; }
        __syncthreads();
    }
    if (tid == 0) {
        float inv = 1.f / (BB * NP);
        float mu = ss[0] * inv;
        float var = ss2[0] * inv - mu * mu;
        g_buf[O_MU + c] = mu;
        g_buf[O_ISTD + c] = rsqrtf(var + 1e-5f);
    }
}

// ---------------- bn+relu + transpose + split: h[c][n] -> h2[n][c] fp16 h/m ----------------
__global__ void bnrelu_kernel(const float* __restrict__ gamma, const float* __restrict__ beta) {
    __shared__ float t[32][33];
    int b = blockIdx.z, cbase = blockIdx.y * 32, nbase = blockIdx.x * 32;
    int tid = threadIdx.x;
    const float* hsrc = g_buf + O_H + (size_t)b * C2 * NP;
#pragma unroll
    for (int i = tid; i < 1024; i += 256) {
        int c = i >> 5, n = i & 31;
        t[c][n] = hsrc[(size_t)(cbase + c) * NP + nbase + n];
    }
    __syncthreads();
    __half* h2h = (__half*)(g_buf + O_H2H);
    __half* h2m = (__half*)(g_buf + O_H2M);
#pragma unroll
    for (int i = tid; i < 1024; i += 256) {
        int n = i >> 5, c = i & 31;
        int cg = cbase + c;
        float v = t[c][n];
        v = fmaxf(fmaf((v - g_buf[O_MU + cg]) * g_buf[O_ISTD + cg], gamma[cg], beta[cg]), 0.f);
        __half hh = __float2half_rn(v);
        size_t o = ((size_t)b * NP + nbase + n) * C2 + cg;
        h2h[o] = hh;
        h2m[o] = __float2half_rn(v - __half2float(hh));
    }
}

// ---------------- launch ----------------
extern "C" void kernel_launch(void* const* d_in, const int* in_sizes, int n_in,
                              void* d_out, int out_size) {
    (void)in_sizes; (void)n_in; (void)out_size;
    const float* x     = (const float*)d_in[0];
    const float* wq    = (const float*)d_in[1];
    const float* bq    = (const float*)d_in[2];
    const float* wk    = (const float*)d_in[3];
    const float* bk    = (const float*)d_in[4];
    const float* wv    = (const float*)d_in[5];
    const float* bv    = (const float*)d_in[6];
    const float* wm    = (const float*)d_in[7];
    const float* bm    = (const float*)d_in[8];
    const float* w1    = (const float*)d_in[9];
    const float* b1    = (const float*)d_in[10];
    const float* gamma = (const float*)d_in[11];
    const float* beta  = (const float*)d_in[12];
    const float* w2    = (const float*)d_in[13];
    const float* b2    = (const float*)d_in[14];
    float* out = (float*)d_out;

    float* base = nullptr;
    cudaGetSymbolAddress((void**)&base, g_buf);
    float* p_h = base + O_H;

    cudaFuncSetAttribute(pd_mma_kernel, cudaFuncAttributeMaxDynamicSharedMemorySize, PD_SMEM);
    cudaFuncSetAttribute(conv_mma<0>, cudaFuncAttributeMaxDynamicSharedMemorySize, CONV_SMEM);
    cudaFuncSetAttribute(conv_mma<1>, cudaFuncAttributeMaxDynamicSharedMemorySize, CONV_SMEM);
    cudaFuncSetAttribute(conv_mma<2>, cudaFuncAttributeMaxDynamicSharedMemorySize, CONV_SMEM);
    cudaFuncSetAttribute(conv_mma<3>, cudaFuncAttributeMaxDynamicSharedMemorySize, CONV_SMEM);
    cudaFuncSetAttribute(topk_kernel, cudaFuncAttributeMaxDynamicSharedMemorySize, TOPK_SMEM);

    wsplit_kernel<<<(WTOT + 255) / 256, 256>>>(wq, wk, wv, wm, w1, w2);
    prep_kernel<<<dim3(NP / 64, CC / 32, BB), 256>>>(x);
    xx_kernel<<<(BB * NP + 255) / 256, 256>>>(x);

    conv_mma<0><<<dim3(NP / 128, 3, BB), 256, CONV_SMEM>>>(bq, bk, bv, nullptr, nullptr);

    pd_mma_kernel<<<dim3(136, BB), 256, PD_SMEM>>>();
    topk_kernel<<<BB * NP / 8, 256, TOPK_SMEM>>>();
    attn_kernel<<<BB * NP / 8, 256>>>();

    conv_mma<1><<<dim3(NP / 128, 1, BB), 256, CONV_SMEM>>>(bm, nullptr, nullptr, nullptr, nullptr);
    conv_mma<2><<<dim3(NP / 128, 2, BB), 256, CONV_SMEM>>>(b1, nullptr, nullptr, nullptr, p_h);

    bn_stats_kernel<<<C2, 256>>>();
    bnrelu_kernel<<<dim3(NP / 32, C2 / 32, BB), 256>>>(gamma, beta);

    conv_mma<3><<<dim3(NP / 128, 1, BB), 256, CONV_SMEM>>>(b2, nullptr, nullptr, x, out);
}

// round 7
// speedup vs baseline: 1.5338x; 1.0148x over previous
#include <cuda_runtime.h>
#include <cuda_fp16.h>
#include <math.h>
#include <stdint.h>

#define BB 2
#define CC 128
#define NP 2048
#define KNN 20
#define C2 256

// packed weight-split offsets (halfs)
#define WOFF_Q 0
#define WOFF_K 16384
#define WOFF_V 32768
#define WOFF_M 49152
#define WOFF_1 65536
#define WOFF_2 131072
#define WTOT   163840

// ---------------- scratch arena (floats) ----------------
#define O_QT   0                               // 3 * B*N*C fp32 (q,k,v transposed [b][n][c])
#define O_XX   (O_QT + 3*BB*NP*CC)
#define O_H    (O_XX + BB*NP)                  // B*2C*N fp32 (w1 out, [b][c][n])
#define O_MU   (O_H + BB*C2*NP)
#define O_ISTD (O_MU + C2)
#define O_IDX  (O_ISTD + C2)                   // B*N*KNN ints
#define O_XH   (O_IDX + BB*NP*KNN)             // halfs [b][n][c]
#define O_XM   (O_XH + BB*NP*CC/2)
#define O_AVH  (O_XM + BB*NP*CC/2)
#define O_AVM  (O_AVH + BB*NP*CC/2)
#define O_A2H  (O_AVM + BB*NP*CC/2)
#define O_A2M  (O_A2H + BB*NP*CC/2)
#define O_H2H  (O_A2M + BB*NP*CC/2)            // halfs [b][n][2C]
#define O_H2M  (O_H2H + BB*NP*C2/2)
#define O_WH   (O_H2M + BB*NP*C2/2)            // packed weight halves
#define O_WM2  (O_WH + WTOT/2)
#define O_PD   (O_WM2 + WTOT/2)
#define TOTALF (O_PD + (size_t)BB*NP*NP)

__device__ __align__(16) float g_buf[TOTALF];

__device__ __forceinline__ uint32_t smem_u32(const void* p) {
    uint32_t a;
    asm("{ .reg .u64 t; cvta.to.shared.u64 t, %1; cvt.u32.u64 %0, t; }" : "=r"(a) : "l"(p));
    return a;
}

// ---------------- xx[b][n] = sum_c x^2 ----------------
__global__ void xx_kernel(const float* __restrict__ x) {
    int i = blockIdx.x * blockDim.x + threadIdx.x;
    if (i >= BB * NP) return;
    int b = i / NP, n = i - b * NP;
    const float* xb = x + (size_t)b * CC * NP + n;
    float s = 0.f;
#pragma unroll 8
    for (int c = 0; c < CC; c++) { float v = xb[(size_t)c * NP]; s = fmaf(v, v, s); }
    g_buf[O_XX + i] = s;
}

// ---------------- transpose + 2-way fp16 split: xT_{h,m}[b][n][c] ----------------
__global__ void prep_kernel(const float* __restrict__ x) {
    __shared__ float ts[32][65];
    int b = blockIdx.z;
    int cbase = blockIdx.y * 32, nbase = blockIdx.x * 64;
    int tid = threadIdx.x;
    __half* xh = reinterpret_cast<__half*>(g_buf + O_XH);
    __half* xm = reinterpret_cast<__half*>(g_buf + O_XM);
#pragma unroll
    for (int i = 0; i < 8; i++) {
        int idx = tid + i * 256;
        int cr = idx >> 6, nn = idx & 63;
        ts[cr][nn] = x[(size_t)b * CC * NP + (size_t)(cbase + cr) * NP + nbase + nn];
    }
    __syncthreads();
#pragma unroll
    for (int i = 0; i < 8; i++) {
        int idx = tid + i * 256;
        int nr = idx >> 5, cc = idx & 31;
        float v = ts[cc][nr];
        __half h1 = __float2half_rn(v);
        __half h2 = __float2half_rn(v - __half2float(h1));
        size_t o = ((size_t)b * NP + nbase + nr) * CC + cbase + cc;
        xh[o] = h1; xm[o] = h2;
    }
}

// ---------------- split all weights to fp16 h/m ----------------
__global__ void wsplit_kernel(const float* __restrict__ wq, const float* __restrict__ wk,
                              const float* __restrict__ wv, const float* __restrict__ wmp,
                              const float* __restrict__ w1, const float* __restrict__ w2) {
    int i = blockIdx.x * 256 + threadIdx.x;
    if (i >= WTOT) return;
    float v;
    if (i < 16384) v = wq[i];
    else if (i < 32768) v = wk[i - 16384];
    else if (i < 49152) v = wv[i - 32768];
    else if (i < 65536) v = wmp[i - 49152];
    else if (i < 131072) v = w1[i - 65536];
    else v = w2[i - 131072];
    __half h = __float2half_rn(v);
    reinterpret_cast<__half*>(g_buf + O_WH)[i] = h;
    reinterpret_cast<__half*>(g_buf + O_WM2)[i] = __float2half_rn(v - __half2float(h));
}

// ---------------- pd via mma.sync HMMA: D ~ hh + hm + mh (mm dropped) ----------------
#define LDA 264
#define PD_SMEM (1024 + 2 * 128 * LDA * 2)

__global__ void __launch_bounds__(256, 1) pd_mma_kernel() {
    extern __shared__ char ps[];
    float* xxi_s = (float*)ps;
    float* xxj_s = (float*)(ps + 512);
    __half* As = (__half*)(ps + 1024);
    __half* Bs = As + 128 * LDA;

    int tid = threadIdx.x, lane = tid & 31, wid = tid >> 5;
    int b = blockIdx.y;
    int t = blockIdx.x;
    int i = 0;
    while (t >= 16 - i) { t -= 16 - i; i++; }
    int j = i + t;
    int ibase = i * 128, jbase = j * 128;

    const __half* xh = reinterpret_cast<const __half*>(g_buf + O_XH);
    const __half* xm = reinterpret_cast<const __half*>(g_buf + O_XM);

    {
        const __half* srcs[4] = { xh + ((size_t)b * NP + ibase) * CC,
                                  xm + ((size_t)b * NP + ibase) * CC,
                                  xh + ((size_t)b * NP + jbase) * CC,
                                  xm + ((size_t)b * NP + jbase) * CC };
        __half* dsts[4] = { As, As + 128, Bs, Bs + 128 };
#pragma unroll
        for (int s = 0; s < 4; s++) {
            const __half* src = srcs[s];
            __half* dst = dsts[s];
#pragma unroll
            for (int idx = tid; idx < 2048; idx += 256) {
                int row = idx >> 4, ch = idx & 15;
                *(uint4*)(dst + (size_t)row * LDA + ch * 8) =
                    *(const uint4*)(src + (size_t)row * CC + ch * 8);
            }
        }
    }
    if (tid < 128) xxi_s[tid] = g_buf[O_XX + b * NP + ibase + tid];
    else           xxj_s[tid - 128] = g_buf[O_XX + b * NP + jbase + (tid - 128)];
    __syncthreads();

    int mw = wid & 1, nw = wid >> 1;
    uint32_t a_s0 = smem_u32(As + (size_t)(mw * 64) * LDA);
    uint32_t b_s0 = smem_u32(Bs + (size_t)(nw * 32) * LDA);

    float acc[4][4][4];
#pragma unroll
    for (int a1 = 0; a1 < 4; a1++)
#pragma unroll
        for (int a2 = 0; a2 < 4; a2++)
#pragma unroll
            for (int a3 = 0; a3 < 4; a3++) acc[a1][a2][a3] = 0.f;

    int lrow = lane & 15, lcol8 = (lane >> 4) * 8;
    const int ACOL[3] = {0, 0, 128};
    const int BCOL[3] = {0, 128, 0};

#pragma unroll
    for (int seg = 0; seg < 3; seg++) {
#pragma unroll
        for (int k16 = 0; k16 < 8; k16++) {
            int akc = ACOL[seg] + k16 * 16 + lcol8;
            int bkc = BCOL[seg] + k16 * 16 + lcol8;
            uint32_t arg[4][4];
#pragma unroll
            for (int mi = 0; mi < 4; mi++) {
                uint32_t addr = a_s0 + (uint32_t)(((mi * 16 + lrow) * LDA + akc) * 2);
                asm volatile("ldmatrix.sync.aligned.m8n8.x4.shared.b16 {%0,%1,%2,%3}, [%4];"
                             : "=r"(arg[mi][0]), "=r"(arg[mi][1]), "=r"(arg[mi][2]), "=r"(arg[mi][3])
                             : "r"(addr));
            }
            uint32_t brg[2][4];
#pragma unroll
            for (int nh = 0; nh < 2; nh++) {
                uint32_t addr = b_s0 + (uint32_t)(((nh * 16 + lrow) * LDA + bkc) * 2);
                asm volatile("ldmatrix.sync.aligned.m8n8.x4.shared.b16 {%0,%1,%2,%3}, [%4];"
                             : "=r"(brg[nh][0]), "=r"(brg[nh][1]), "=r"(brg[nh][2]), "=r"(brg[nh][3])
                             : "r"(addr));
            }
#pragma unroll
            for (int mi = 0; mi < 4; mi++)
#pragma unroll
                for (int ni = 0; ni < 4; ni++) {
                    uint32_t b0 = brg[ni >> 1][ni & 1];
                    uint32_t b1 = brg[ni >> 1][2 + (ni & 1)];
                    asm volatile(
                        "mma.sync.aligned.m16n8k16.row.col.f32.f16.f16.f32 "
                        "{%0,%1,%2,%3}, {%4,%5,%6,%7}, {%8,%9}, {%0,%1,%2,%3};"
                        : "+f"(acc[mi][ni][0]), "+f"(acc[mi][ni][1]),
                          "+f"(acc[mi][ni][2]), "+f"(acc[mi][ni][3])
                        : "r"(arg[mi][0]), "r"(arg[mi][1]), "r"(arg[mi][2]), "r"(arg[mi][3]),
                          "r"(b0), "r"(b1));
                }
        }
    }

    int g = lane >> 2, q = lane & 3;
    float* pdb = g_buf + O_PD + (size_t)b * NP * NP;
#pragma unroll
    for (int mi = 0; mi < 4; mi++)
#pragma unroll
        for (int ni = 0; ni < 4; ni++) {
            int r0 = mw * 64 + mi * 16 + g;
            int c0 = nw * 32 + ni * 8 + q * 2;
            float xj0 = xxj_s[c0], xj1 = xxj_s[c0 + 1];
            float xi0 = xxi_s[r0], xi1 = xxi_s[r0 + 8];
            float2 v01, v23;
            v01.x = 2.f * acc[mi][ni][0] - xi0 - xj0;
            v01.y = 2.f * acc[mi][ni][1] - xi0 - xj1;
            v23.x = 2.f * acc[mi][ni][2] - xi1 - xj0;
            v23.y = 2.f * acc[mi][ni][3] - xi1 - xj1;
            *(float2*)(pdb + (size_t)(ibase + r0) * NP + jbase + c0) = v01;
            *(float2*)(pdb + (size_t)(ibase + r0 + 8) * NP + jbase + c0) = v23;
        }

    __syncthreads();
    if (ibase != jbase) {
        float* patch = (float*)(ps + 1024) + (size_t)wid * 32 * 68;
#pragma unroll
        for (int mi = 0; mi < 4; mi++)
#pragma unroll
            for (int ni = 0; ni < 4; ni++) {
                int rl = mi * 16 + g;
                int cl = ni * 8 + q * 2;
                int r0 = mw * 64 + rl, c0 = nw * 32 + cl;
                float xj0 = xxj_s[c0], xj1 = xxj_s[c0 + 1];
                float xi0 = xxi_s[r0], xi1 = xxi_s[r0 + 8];
                patch[(cl + 0) * 68 + rl]     = 2.f * acc[mi][ni][0] - xi0 - xj0;
                patch[(cl + 1) * 68 + rl]     = 2.f * acc[mi][ni][1] - xi0 - xj1;
                patch[(cl + 0) * 68 + rl + 8] = 2.f * acc[mi][ni][2] - xi1 - xj0;
                patch[(cl + 1) * 68 + rl + 8] = 2.f * acc[mi][ni][3] - xi1 - xj1;
            }
        __syncwarp();
#pragma unroll
        for (int cc = 0; cc < 32; cc++) {
            float2 val = *(float2*)(patch + cc * 68 + lane * 2);
            *(float2*)(pdb + (size_t)(jbase + nw * 32 + cc) * NP + ibase + mw * 64 + lane * 2) = val;
        }
    }
}

// ---------------- HMMA conv1x1 ----------------
#define CLDA 264
#define CONV_SMEM (2 * 128 * CLDA * 2)

template<int MODE>
__global__ void __launch_bounds__(256, 1) conv_mma(const float* __restrict__ bias0,
                                                   const float* __restrict__ bias1,
                                                   const float* __restrict__ bias2,
                                                   const float* __restrict__ resid,
                                                   float* __restrict__ outp) {
    extern __shared__ char cs[];
    __half* As = (__half*)cs;
    __half* Bs = As + 128 * CLDA;
    int tid = threadIdx.x, lane = tid & 31, wid = tid >> 5;
    int b = blockIdx.z, nbase = blockIdx.x * 128;
    int yb = blockIdx.y;

    const __half* WH = reinterpret_cast<const __half*>(g_buf + O_WH);
    const __half* WM = reinterpret_cast<const __half*>(g_buf + O_WM2);
    int woff, wstride, obase = 0;
    if (MODE == 0)      { woff = yb * 16384; wstride = 128; }
    else if (MODE == 1) { woff = WOFF_M; wstride = 128; }
    else if (MODE == 2) { woff = WOFF_1 + yb * 128 * 256; wstride = 256; obase = yb * 128; }
    else                { woff = WOFF_2; wstride = 256; }
    const int KCH = (MODE >= 2) ? 2 : 1;

    float acc[4][4][4];
#pragma unroll
    for (int a1 = 0; a1 < 4; a1++)
#pragma unroll
        for (int a2 = 0; a2 < 4; a2++)
#pragma unroll
            for (int a3 = 0; a3 < 4; a3++) acc[a1][a2][a3] = 0.f;

    int mw = wid & 1, nw = wid >> 1;
    int lrow = lane & 15, lcol8 = (lane >> 4) * 8;
    uint32_t a_s0 = smem_u32(As + (size_t)(mw * 64) * CLDA);
    uint32_t b_s0 = smem_u32(Bs + (size_t)(nw * 32) * CLDA);

#pragma unroll
    for (int kc = 0; kc < KCH; kc++) {
        const __half* wsh = WH + woff + kc * 128;
        const __half* wsm = WM + woff + kc * 128;
#pragma unroll
        for (int idx = tid; idx < 2048; idx += 256) {
            int row = idx >> 4, ch = idx & 15;
            *(uint4*)(As + (size_t)row * CLDA + ch * 8) =
                *(const uint4*)(wsh + (size_t)row * wstride + ch * 8);
            *(uint4*)(As + (size_t)row * CLDA + 128 + ch * 8) =
                *(const uint4*)(wsm + (size_t)row * wstride + ch * 8);
        }
        const __half *bh, *bm; int bstr;
        if (MODE == 0) { bh = (const __half*)(g_buf + O_XH); bm = (const __half*)(g_buf + O_XM); bstr = 128; }
        else if (MODE == 1) { bh = (const __half*)(g_buf + O_AVH); bm = (const __half*)(g_buf + O_AVM); bstr = 128; }
        else if (MODE == 2) {
            if (kc == 0) { bh = (const __half*)(g_buf + O_XH); bm = (const __half*)(g_buf + O_XM); }
            else         { bh = (const __half*)(g_buf + O_A2H); bm = (const __half*)(g_buf + O_A2M); }
            bstr = 128;
        } else {
            bh = (const __half*)(g_buf + O_H2H) + kc * 128;
            bm = (const __half*)(g_buf + O_H2M) + kc * 128;
            bstr = 256;
        }
        const __half* bhp = bh + (size_t)(b * NP + nbase) * bstr;
        const __half* bmp = bm + (size_t)(b * NP + nbase) * bstr;
#pragma unroll
        for (int idx = tid; idx < 2048; idx += 256) {
            int row = idx >> 4, ch = idx & 15;
            *(uint4*)(Bs + (size_t)row * CLDA + ch * 8) =
                *(const uint4*)(bhp + (size_t)row * bstr + ch * 8);
            *(uint4*)(Bs + (size_t)row * CLDA + 128 + ch * 8) =
                *(const uint4*)(bmp + (size_t)row * bstr + ch * 8);
        }
        __syncthreads();

        const int ACOL[3] = {0, 0, 128};
        const int BCOL[3] = {0, 128, 0};
#pragma unroll
        for (int seg = 0; seg < 3; seg++) {
#pragma unroll
            for (int k16 = 0; k16 < 8; k16++) {
                int akc = ACOL[seg] + k16 * 16 + lcol8;
                int bkc = BCOL[seg] + k16 * 16 + lcol8;
                uint32_t arg[4][4];
#pragma unroll
                for (int mi = 0; mi < 4; mi++) {
                    uint32_t addr = a_s0 + (uint32_t)(((mi * 16 + lrow) * CLDA + akc) * 2);
                    asm volatile("ldmatrix.sync.aligned.m8n8.x4.shared.b16 {%0,%1,%2,%3}, [%4];"
                                 : "=r"(arg[mi][0]), "=r"(arg[mi][1]), "=r"(arg[mi][2]), "=r"(arg[mi][3])
                                 : "r"(addr));
                }
                uint32_t brg[2][4];
#pragma unroll
                for (int nh = 0; nh < 2; nh++) {
                    uint32_t addr = b_s0 + (uint32_t)(((nh * 16 + lrow) * CLDA + bkc) * 2);
                    asm volatile("ldmatrix.sync.aligned.m8n8.x4.shared.b16 {%0,%1,%2,%3}, [%4];"
                                 : "=r"(brg[nh][0]), "=r"(brg[nh][1]), "=r"(brg[nh][2]), "=r"(brg[nh][3])
                                 : "r"(addr));
                }
#pragma unroll
                for (int mi = 0; mi < 4; mi++)
#pragma unroll
                    for (int ni = 0; ni < 4; ni++) {
                        uint32_t b0 = brg[ni >> 1][ni & 1];
                        uint32_t b1 = brg[ni >> 1][2 + (ni & 1)];
                        asm volatile(
                            "mma.sync.aligned.m16n8k16.row.col.f32.f16.f16.f32 "
                            "{%0,%1,%2,%3}, {%4,%5,%6,%7}, {%8,%9}, {%0,%1,%2,%3};"
                            : "+f"(acc[mi][ni][0]), "+f"(acc[mi][ni][1]),
                              "+f"(acc[mi][ni][2]), "+f"(acc[mi][ni][3])
                            : "r"(arg[mi][0]), "r"(arg[mi][1]), "r"(arg[mi][2]), "r"(arg[mi][3]),
                              "r"(b0), "r"(b1));
                    }
            }
        }
        __syncthreads();
    }

    int g = lane >> 2, q = lane & 3;
    if (MODE <= 1) {
        const float* bias_ = (MODE == 0) ? (yb == 0 ? bias0 : yb == 1 ? bias1 : bias2) : bias0;
        float* patch = (float*)cs + (size_t)wid * 32 * 68;
#pragma unroll
        for (int mi = 0; mi < 4; mi++)
#pragma unroll
            for (int ni = 0; ni < 4; ni++) {
                int rl = mi * 16 + g;
                int cl = ni * 8 + q * 2;
                float bs0 = bias_[mw * 64 + rl], bs1 = bias_[mw * 64 + rl + 8];
                patch[(cl + 0) * 68 + rl]     = acc[mi][ni][0] + bs0;
                patch[(cl + 1) * 68 + rl]     = acc[mi][ni][1] + bs0;
                patch[(cl + 0) * 68 + rl + 8] = acc[mi][ni][2] + bs1;
                patch[(cl + 1) * 68 + rl + 8] = acc[mi][ni][3] + bs1;
            }
        __syncwarp();
        if (MODE == 0) {
            float* Y = g_buf + O_QT + (size_t)yb * BB * NP * CC;
#pragma unroll
            for (int r = 0; r < 32; r++) {
                int n = nbase + nw * 32 + r;
                *(float2*)(Y + ((size_t)b * NP + n) * CC + mw * 64 + lane * 2) =
                    *(float2*)(patch + r * 68 + lane * 2);
            }
        } else {
            __half* Yh = (__half*)(g_buf + O_A2H);
            __half* Ym = (__half*)(g_buf + O_A2M);
#pragma unroll
            for (int r = 0; r < 32; r++) {
                int n = nbase + nw * 32 + r;
                float2 v = *(float2*)(patch + r * 68 + lane * 2);
                __half h0 = __float2half_rn(v.x), h1 = __float2half_rn(v.y);
                __half m0 = __float2half_rn(v.x - __half2float(h0));
                __half m1 = __float2half_rn(v.y - __half2float(h1));
                size_t o = ((size_t)b * NP + n) * CC + mw * 64 + lane * 2;
                *(__half2*)(Yh + o) = __halves2half2(h0, h1);
                *(__half2*)(Ym + o) = __halves2half2(m0, m1);
            }
        }
    } else {
        const float* bias_ = bias0;
        float* Yb = outp + (size_t)b * ((MODE == 2) ? C2 * NP : CC * NP);
#pragma unroll
        for (int mi = 0; mi < 4; mi++)
#pragma unroll
            for (int ni = 0; ni < 4; ni++) {
                int r0 = obase + mw * 64 + mi * 16 + g;
                int c0 = nbase + nw * 32 + ni * 8 + q * 2;
                float bs0 = bias_[r0], bs1 = bias_[r0 + 8];
                float2 v01, v23;
                v01.x = acc[mi][ni][0] + bs0; v01.y = acc[mi][ni][1] + bs0;
                v23.x = acc[mi][ni][2] + bs1; v23.y = acc[mi][ni][3] + bs1;
                if (MODE == 3) {
                    const float* rb = resid + (size_t)b * CC * NP;
                    v01.x += rb[(size_t)r0 * NP + c0];
                    v01.y += rb[(size_t)r0 * NP + c0 + 1];
                    v23.x += rb[(size_t)(r0 + 8) * NP + c0];
                    v23.y += rb[(size_t)(r0 + 8) * NP + c0 + 1];
                }
                *(float2*)(Yb + (size_t)r0 * NP + c0) = v01;
                *(float2*)(Yb + (size_t)(r0 + 8) * NP + c0) = v23;
            }
    }
}

// ---------------- warp-per-row top-20 ----------------
#define TOPK_SMEM (8 * 2048 * 4)
__global__ void __launch_bounds__(256) topk_kernel() {
    extern __shared__ float srows[];
    const unsigned FULL = 0xffffffffu;
    int tid = threadIdx.x, lane = tid & 31, wid = tid >> 5;
    int rowbase = blockIdx.x * 8;
    const float4* g4 = (const float4*)(g_buf + O_PD + (size_t)rowbase * NP);
    float4* s4 = (float4*)srows;
#pragma unroll
    for (int i = tid; i < 8 * 512; i += 256) s4[i] = g4[i];
    __syncthreads();

    float* s = srows + wid * 2048 + lane * 64;
    float bv = -3.4e38f; int bi = 0;
#pragma unroll
    for (int k4 = 0; k4 < 16; k4++) {
        float4 vv = *(float4*)(s + k4 * 4);
        if (vv.x > bv) { bv = vv.x; bi = k4 * 4 + 0; }
        if (vv.y > bv) { bv = vv.y; bi = k4 * 4 + 1; }
        if (vv.z > bv) { bv = vv.z; bi = k4 * 4 + 2; }
        if (vv.w > bv) { bv = vv.w; bi = k4 * 4 + 3; }
    }
    int gbase = lane * 64;
    int* idxout = reinterpret_cast<int*>(g_buf + O_IDX) + (size_t)(rowbase + wid) * KNN;

    for (int it = 0; it < KNN; it++) {
        float cv = bv; int ci = gbase + bi;
#pragma unroll
        for (int off = 16; off; off >>= 1) {
            float ov = __shfl_down_sync(FULL, cv, off);
            int oi = __shfl_down_sync(FULL, ci, off);
            if (ov > cv || (ov == cv && oi < ci)) { cv = ov; ci = oi; }
        }
        ci = __shfl_sync(FULL, ci, 0);
        if (lane == 0) idxout[it] = ci;
        if ((ci >> 6) == lane) {
            s[ci & 63] = -3.4e38f;
            bv = -3.4e38f; bi = 0;
#pragma unroll
            for (int k4 = 0; k4 < 16; k4++) {
                float4 vv = *(float4*)(s + k4 * 4);
                if (vv.x > bv) { bv = vv.x; bi = k4 * 4 + 0; }
                if (vv.y > bv) { bv = vv.y; bi = k4 * 4 + 1; }
                if (vv.z > bv) { bv = vv.z; bi = k4 * 4 + 2; }
                if (vv.w > bv) { bv = vv.w; bi = k4 * 4 + 3; }
            }
        }
    }
}

// ---------------- sparse mutual-kNN attention: one warp per (b,n) ----------------
__global__ void attn_kernel() {
    const unsigned FULL = 0xffffffffu;
    int gwarp = (blockIdx.x * blockDim.x + threadIdx.x) >> 5;
    int lane = threadIdx.x & 31;
    int b = gwarp / NP, n = gwarp - b * NP;

    const float* qT = g_buf + O_QT;
    const float* kT = g_buf + O_QT + BB * NP * CC;
    const float* vT = g_buf + O_QT + 2 * BB * NP * CC;
    const int* idx = reinterpret_cast<const int*>(g_buf + O_IDX);

    const float* qrow = qT + ((size_t)b * NP + n) * CC;
    float q0 = qrow[lane], q1 = qrow[lane + 32], q2 = qrow[lane + 64], q3 = qrow[lane + 96];

    int mj = 0, act = 0;
    if (lane < KNN) {
        mj = idx[(b * NP + n) * KNN + lane];
        const int* lst = idx + (size_t)(b * NP + mj) * KNN;
#pragma unroll
        for (int tt = 0; tt < KNN; tt++) act |= (lst[tt] == n);
    }
    unsigned amask = __ballot_sync(FULL, act);

    float sc[4] = {0.f, 0.f, 0.f, 0.f};
    for (int jj = 0; jj < KNN; jj++) {
        if (!((amask >> jj) & 1)) continue;
        int m = __shfl_sync(FULL, mj, jj);
        const float* krow = kT + ((size_t)b * NP + m) * CC;
        float p0 = q0 * krow[lane], p1 = q1 * krow[lane + 32];
        float p2 = q2 * krow[lane + 64], p3 = q3 * krow[lane + 96];
#pragma unroll
        for (int off = 16; off; off >>= 1) {
            p0 += __shfl_xor_sync(FULL, p0, off);
            p1 += __shfl_xor_sync(FULL, p1, off);
            p2 += __shfl_xor_sync(FULL, p2, off);
            p3 += __shfl_xor_sync(FULL, p3, off);
        }
        if (lane == jj) { sc[0] = p0; sc[1] = p1; sc[2] = p2; sc[3] = p3; }
    }

    const float scale = 0.17677669529663687f;
    bool live = (lane < KNN) && ((amask >> lane) & 1);
    float p[4];
#pragma unroll
    for (int hh = 0; hh < 4; hh++) {
        float v = live ? sc[hh] * scale : -3.4e38f;
        float mx = v;
#pragma unroll
        for (int off = 16; off; off >>= 1) mx = fmaxf(mx, __shfl_xor_sync(FULL, mx, off));
        float e = live ? expf(v - mx) : 0.f;
        float sm = e;
#pragma unroll
        for (int off = 16; off; off >>= 1) sm += __shfl_xor_sync(FULL, sm, off);
        p[hh] = e / sm;
    }

    float a0 = 0.f, a1 = 0.f, a2 = 0.f, a3 = 0.f;
    for (int jj = 0; jj < KNN; jj++) {
        if (!((amask >> jj) & 1)) continue;
        int m = __shfl_sync(FULL, mj, jj);
        float w0 = __shfl_sync(FULL, p[0], jj);
        float w1 = __shfl_sync(FULL, p[1], jj);
        float w2 = __shfl_sync(FULL, p[2], jj);
        float w3 = __shfl_sync(FULL, p[3], jj);
        const float* vrow = vT + ((size_t)b * NP + m) * CC;
        a0 = fmaf(w0, vrow[lane], a0);
        a1 = fmaf(w1, vrow[lane + 32], a1);
        a2 = fmaf(w2, vrow[lane + 64], a2);
        a3 = fmaf(w3, vrow[lane + 96], a3);
    }
    __half* avh = (__half*)(g_buf + O_AVH);
    __half* avm = (__half*)(g_buf + O_AVM);
    size_t o = ((size_t)b * NP + n) * CC;
    float vals[4] = {a0, a1, a2, a3};
#pragma unroll
    for (int c = 0; c < 4; c++) {
        __half hh = __float2half_rn(vals[c]);
        avh[o + c * 32 + lane] = hh;
        avm[o + c * 32 + lane] = __float2half_rn(vals[c] - __half2float(hh));
    }
}

// ---------------- batchnorm statistics ----------------
__global__ void bn_stats_kernel() {
    __shared__ float ss[256], ss2[256];
    int c = blockIdx.x, tid = threadIdx.x;
    float s = 0.f, s2 = 0.f;
    for (int bn = tid; bn < BB * NP; bn += 256) {
        int b = bn >> 11, n = bn & (NP - 1);
        float v = g_buf[O_H + (size_t)b * C2 * NP + (size_t)c * NP + n];
        s += v; s2 = fmaf(v, v, s2);
    }
    ss[tid] = s; ss2[tid] = s2;
    __syncthreads();
    for (int off = 128; off; off >>= 1) {
        if (tid < off) { ss[tid] += ss[tid + off]; ss2[tid] += ss2[tid + off]; }
        __syncthreads();
    }
    if (tid == 0) {
        float inv = 1.f / (BB * NP);
        float mu = ss[0] * inv;
        float var = ss2[0] * inv - mu * mu;
        g_buf[O_MU + c] = mu;
        g_buf[O_ISTD + c] = rsqrtf(var + 1e-5f);
    }
}

// ---------------- bn+relu + transpose + split ----------------
__global__ void bnrelu_kernel(const float* __restrict__ gamma, const float* __restrict__ beta) {
    __shared__ float t[32][33];
    int b = blockIdx.z, cbase = blockIdx.y * 32, nbase = blockIdx.x * 32;
    int tid = threadIdx.x;
    const float* hsrc = g_buf + O_H + (size_t)b * C2 * NP;
#pragma unroll
    for (int i = tid; i < 1024; i += 256) {
        int c = i >> 5, n = i & 31;
        t[c][n] = hsrc[(size_t)(cbase + c) * NP + nbase + n];
    }
    __syncthreads();
    __half* h2h = (__half*)(g_buf + O_H2H);
    __half* h2m = (__half*)(g_buf + O_H2M);
#pragma unroll
    for (int i = tid; i < 1024; i += 256) {
        int n = i >> 5, c = i & 31;
        int cg = cbase + c;
        float v = t[c][n];
        v = fmaxf(fmaf((v - g_buf[O_MU + cg]) * g_buf[O_ISTD + cg], gamma[cg], beta[cg]), 0.f);
        __half hh = __float2half_rn(v);
        size_t o = ((size_t)b * NP + nbase + n) * C2 + cg;
        h2h[o] = hh;
        h2m[o] = __float2half_rn(v - __half2float(hh));
    }
}

// ---------------- launch ----------------
extern "C" void kernel_launch(void* const* d_in, const int* in_sizes, int n_in,
                              void* d_out, int out_size) {
    (void)in_sizes; (void)n_in; (void)out_size;
    const float* x     = (const float*)d_in[0];
    const float* wq    = (const float*)d_in[1];
    const float* bq    = (const float*)d_in[2];
    const float* wk    = (const float*)d_in[3];
    const float* bk    = (const float*)d_in[4];
    const float* wv    = (const float*)d_in[5];
    const float* bv    = (const float*)d_in[6];
    const float* wm    = (const float*)d_in[7];
    const float* bm    = (const float*)d_in[8];
    const float* w1    = (const float*)d_in[9];
    const float* b1    = (const float*)d_in[10];
    const float* gamma = (const float*)d_in[11];
    const float* beta  = (const float*)d_in[12];
    const float* w2    = (const float*)d_in[13];
    const float* b2    = (const float*)d_in[14];
    float* out = (float*)d_out;

    float* base = nullptr;
    cudaGetSymbolAddress((void**)&base, g_buf);
    float* p_h = base + O_H;

    static cudaStream_t s2 = nullptr;
    static cudaEvent_t evF = nullptr, evJ = nullptr;
    if (s2 == nullptr) {
        cudaStreamCreateWithFlags(&s2, cudaStreamNonBlocking);
        cudaEventCreateWithFlags(&evF, cudaEventDisableTiming);
        cudaEventCreateWithFlags(&evJ, cudaEventDisableTiming);
    }

    cudaFuncSetAttribute(pd_mma_kernel, cudaFuncAttributeMaxDynamicSharedMemorySize, PD_SMEM);
    cudaFuncSetAttribute(conv_mma<0>, cudaFuncAttributeMaxDynamicSharedMemorySize, CONV_SMEM);
    cudaFuncSetAttribute(conv_mma<1>, cudaFuncAttributeMaxDynamicSharedMemorySize, CONV_SMEM);
    cudaFuncSetAttribute(conv_mma<2>, cudaFuncAttributeMaxDynamicSharedMemorySize, CONV_SMEM);
    cudaFuncSetAttribute(conv_mma<3>, cudaFuncAttributeMaxDynamicSharedMemorySize, CONV_SMEM);
    cudaFuncSetAttribute(topk_kernel, cudaFuncAttributeMaxDynamicSharedMemorySize, TOPK_SMEM);

    wsplit_kernel<<<(WTOT + 255) / 256, 256>>>(wq, wk, wv, wm, w1, w2);
    prep_kernel<<<dim3(NP / 64, CC / 32, BB), 256>>>(x);
    xx_kernel<<<(BB * NP + 255) / 256, 256>>>(x);

    // fork: qkv conv on side stream, pd+topk on main stream (independent until attn)
    cudaEventRecord(evF, 0);
    cudaStreamWaitEvent(s2, evF, 0);
    conv_mma<0><<<dim3(NP / 128, 3, BB), 256, CONV_SMEM, s2>>>(bq, bk, bv, nullptr, nullptr);
    cudaEventRecord(evJ, s2);

    pd_mma_kernel<<<dim3(136, BB), 256, PD_SMEM>>>();
    topk_kernel<<<BB * NP / 8, 256, TOPK_SMEM>>>();

    cudaStreamWaitEvent(0, evJ, 0);
    attn_kernel<<<BB * NP / 8, 256>>>();

    conv_mma<1><<<dim3(NP / 128, 1, BB), 256, CONV_SMEM>>>(bm, nullptr, nullptr, nullptr, nullptr);
    conv_mma<2><<<dim3(NP / 128, 2, BB), 256, CONV_SMEM>>>(b1, nullptr, nullptr, nullptr, p_h);

    bn_stats_kernel<<<C2, 256>>>();
    bnrelu_kernel<<<dim3(NP / 32, C2 / 32, BB), 256>>>(gamma, beta);

    conv_mma<3><<<dim3(NP / 128, 1, BB), 256, CONV_SMEM>>>(b2, nullptr, nullptr, x, out);
}

// round 9
// speedup vs baseline: 1.6428x; 1.0711x over previous
#include <cuda_runtime.h>
#include <cuda_fp16.h>
#include <math.h>
#include <stdint.h>

#define BB 2
#define CC 128
#define NP 2048
#define KNN 20
#define C2 256

// packed weight-split offsets (halfs)
#define WOFF_Q 0
#define WOFF_K 16384
#define WOFF_V 32768
#define WOFF_M 49152
#define WOFF_1 65536
#define WOFF_2 131072
#define WTOT   163840

// ---------------- scratch arena (floats) ----------------
#define O_QT   0                               // 3 * B*N*C fp32 (q,k,v transposed [b][n][c])
#define O_XX   (O_QT + 3*BB*NP*CC)
#define O_H    (O_XX + BB*NP)                  // B*2C*N fp32 (w1 out, [b][c][n])
#define O_MU   (O_H + BB*C2*NP)
#define O_ISTD (O_MU + C2)
#define O_B1P  (O_ISTD + C2)                   // fused bias b1' (256)
#define O_IDX  (O_B1P + C2)                    // B*N*KNN ints
#define O_XH   (O_IDX + BB*NP*KNN)             // halfs [b][n][c]
#define O_XM   (O_XH + BB*NP*CC/2)
#define O_AVH  (O_XM + BB*NP*CC/2)
#define O_AVM  (O_AVH + BB*NP*CC/2)
#define O_H2H  (O_AVM + BB*NP*CC/2)            // halfs [b][n][2C]
#define O_H2M  (O_H2H + BB*NP*C2/2)
#define O_WH   (O_H2M + BB*NP*C2/2)            // packed weight halves
#define O_WM2  (O_WH + WTOT/2)
#define O_PD   (O_WM2 + WTOT/2)
#define TOTALF (O_PD + (size_t)BB*NP*NP)

__device__ __align__(16) float g_buf[TOTALF];

__device__ __forceinline__ uint32_t smem_u32(const void* p) {
    uint32_t a;
    asm("{ .reg .u64 t; cvta.to.shared.u64 t, %1; cvt.u32.u64 %0, t; }" : "=r"(a) : "l"(p));
    return a;
}

// ---------------- xx[b][n] = sum_c x^2 ----------------
__global__ void xx_kernel(const float* __restrict__ x) {
    int i = blockIdx.x * blockDim.x + threadIdx.x;
    if (i >= BB * NP) return;
    int b = i / NP, n = i - b * NP;
    const float* xb = x + (size_t)b * CC * NP + n;
    float s = 0.f;
#pragma unroll 8
    for (int c = 0; c < CC; c++) { float v = xb[(size_t)c * NP]; s = fmaf(v, v, s); }
    g_buf[O_XX + i] = s;
}

// ---------------- transpose + 2-way fp16 split: xT_{h,m}[b][n][c] ----------------
__global__ void prep_kernel(const float* __restrict__ x) {
    __shared__ float ts[32][65];
    int b = blockIdx.z;
    int cbase = blockIdx.y * 32, nbase = blockIdx.x * 64;
    int tid = threadIdx.x;
    __half* xh = reinterpret_cast<__half*>(g_buf + O_XH);
    __half* xm = reinterpret_cast<__half*>(g_buf + O_XM);
#pragma unroll
    for (int i = 0; i < 8; i++) {
        int idx = tid + i * 256;
        int cr = idx >> 6, nn = idx & 63;
        ts[cr][nn] = x[(size_t)b * CC * NP + (size_t)(cbase + cr) * NP + nbase + nn];
    }
    __syncthreads();
#pragma unroll
    for (int i = 0; i < 8; i++) {
        int idx = tid + i * 256;
        int nr = idx >> 5, cc = idx & 31;
        float v = ts[cc][nr];
        __half h1 = __float2half_rn(v);
        __half h2 = __float2half_rn(v - __half2float(h1));
        size_t o = ((size_t)b * NP + nbase + nr) * CC + cbase + cc;
        xh[o] = h1; xm[o] = h2;
    }
}

// ---------------- split all weights to fp16 h/m ----------------
__global__ void wsplit_kernel(const float* __restrict__ wq, const float* __restrict__ wk,
                              const float* __restrict__ wv, const float* __restrict__ wmp,
                              const float* __restrict__ w1, const float* __restrict__ w2) {
    int i = blockIdx.x * 256 + threadIdx.x;
    if (i >= WTOT) return;
    float v;
    if (i < 16384) v = wq[i];
    else if (i < 32768) v = wk[i - 16384];
    else if (i < 49152) v = wv[i - 32768];
    else if (i < 65536) v = wmp[i - 49152];
    else if (i < 131072) v = w1[i - 65536];
    else v = w2[i - 131072];
    __half h = __float2half_rn(v);
    reinterpret_cast<__half*>(g_buf + O_WH)[i] = h;
    reinterpret_cast<__half*>(g_buf + O_WM2)[i] = __float2half_rn(v - __half2float(h));
}

// ---------------- fold wm into w1: F = w1[:,128:]@wm, b1' = b1 + w1[:,128:]@bm ----------------
__global__ void wfuse_kernel(const float* __restrict__ w1, const float* __restrict__ wm,
                             const float* __restrict__ bm, const float* __restrict__ b1) {
    int o = blockIdx.x;            // 0..255
    int c = threadIdx.x;           // 0..127
    float s = 0.f;
#pragma unroll 8
    for (int k = 0; k < 128; k++)
        s = fmaf(w1[o * 256 + 128 + k], wm[k * 128 + c], s);
    __half h = __float2half_rn(s);
    int i = WOFF_1 + o * 256 + 128 + c;
    reinterpret_cast<__half*>(g_buf + O_WH)[i] = h;
    reinterpret_cast<__half*>(g_buf + O_WM2)[i] = __float2half_rn(s - __half2float(h));
    if (c == 0) {
        float bsum = b1[o];
        for (int k = 0; k < 128; k++) bsum = fmaf(w1[o * 256 + 128 + k], bm[k], bsum);
        g_buf[O_B1P + o] = bsum;
    }
}

// ---------------- pd via mma.sync HMMA: D ~ hh + hm + mh ----------------
#define LDA 264
#define PD_SMEM (1024 + 2 * 128 * LDA * 2)

__global__ void __launch_bounds__(256, 1) pd_mma_kernel() {
    extern __shared__ char ps[];
    float* xxi_s = (float*)ps;
    float* xxj_s = (float*)(ps + 512);
    __half* As = (__half*)(ps + 1024);
    __half* Bs = As + 128 * LDA;

    int tid = threadIdx.x, lane = tid & 31, wid = tid >> 5;
    int b = blockIdx.y;
    int t = blockIdx.x;
    int i = 0;
    while (t >= 16 - i) { t -= 16 - i; i++; }
    int j = i + t;
    int ibase = i * 128, jbase = j * 128;

    const __half* xh = reinterpret_cast<const __half*>(g_buf + O_XH);
    const __half* xm = reinterpret_cast<const __half*>(g_buf + O_XM);

    {
        const __half* srcs[4] = { xh + ((size_t)b * NP + ibase) * CC,
                                  xm + ((size_t)b * NP + ibase) * CC,
                                  xh + ((size_t)b * NP + jbase) * CC,
                                  xm + ((size_t)b * NP + jbase) * CC };
        __half* dsts[4] = { As, As + 128, Bs, Bs + 128 };
#pragma unroll
        for (int s = 0; s < 4; s++) {
            const __half* src = srcs[s];
            __half* dst = dsts[s];
#pragma unroll
            for (int idx = tid; idx < 2048; idx += 256) {
                int row = idx >> 4, ch = idx & 15;
                *(uint4*)(dst + (size_t)row * LDA + ch * 8) =
                    *(const uint4*)(src + (size_t)row * CC + ch * 8);
            }
        }
    }
    if (tid < 128) xxi_s[tid] = g_buf[O_XX + b * NP + ibase + tid];
    else           xxj_s[tid - 128] = g_buf[O_XX + b * NP + jbase + (tid - 128)];
    __syncthreads();

    int mw = wid & 1, nw = wid >> 1;
    uint32_t a_s0 = smem_u32(As + (size_t)(mw * 64) * LDA);
    uint32_t b_s0 = smem_u32(Bs + (size_t)(nw * 32) * LDA);

    float acc[4][4][4];
#pragma unroll
    for (int a1 = 0; a1 < 4; a1++)
#pragma unroll
        for (int a2 = 0; a2 < 4; a2++)
#pragma unroll
            for (int a3 = 0; a3 < 4; a3++) acc[a1][a2][a3] = 0.f;

    int lrow = lane & 15, lcol8 = (lane >> 4) * 8;
    const int ACOL[3] = {0, 0, 128};
    const int BCOL[3] = {0, 128, 0};

#pragma unroll
    for (int seg = 0; seg < 3; seg++) {
#pragma unroll
        for (int k16 = 0; k16 < 8; k16++) {
            int akc = ACOL[seg] + k16 * 16 + lcol8;
            int bkc = BCOL[seg] + k16 * 16 + lcol8;
            uint32_t arg[4][4];
#pragma unroll
            for (int mi = 0; mi < 4; mi++) {
                uint32_t addr = a_s0 + (uint32_t)(((mi * 16 + lrow) * LDA + akc) * 2);
                asm volatile("ldmatrix.sync.aligned.m8n8.x4.shared.b16 {%0,%1,%2,%3}, [%4];"
                             : "=r"(arg[mi][0]), "=r"(arg[mi][1]), "=r"(arg[mi][2]), "=r"(arg[mi][3])
                             : "r"(addr));
            }
            uint32_t brg[2][4];
#pragma unroll
            for (int nh = 0; nh < 2; nh++) {
                uint32_t addr = b_s0 + (uint32_t)(((nh * 16 + lrow) * LDA + bkc) * 2);
                asm volatile("ldmatrix.sync.aligned.m8n8.x4.shared.b16 {%0,%1,%2,%3}, [%4];"
                             : "=r"(brg[nh][0]), "=r"(brg[nh][1]), "=r"(brg[nh][2]), "=r"(brg[nh][3])
                             : "r"(addr));
            }
#pragma unroll
            for (int mi = 0; mi < 4; mi++)
#pragma unroll
                for (int ni = 0; ni < 4; ni++) {
                    uint32_t b0 = brg[ni >> 1][ni & 1];
                    uint32_t b1 = brg[ni >> 1][2 + (ni & 1)];
                    asm volatile(
                        "mma.sync.aligned.m16n8k16.row.col.f32.f16.f16.f32 "
                        "{%0,%1,%2,%3}, {%4,%5,%6,%7}, {%8,%9}, {%0,%1,%2,%3};"
                        : "+f"(acc[mi][ni][0]), "+f"(acc[mi][ni][1]),
                          "+f"(acc[mi][ni][2]), "+f"(acc[mi][ni][3])
                        : "r"(arg[mi][0]), "r"(arg[mi][1]), "r"(arg[mi][2]), "r"(arg[mi][3]),
                          "r"(b0), "r"(b1));
                }
        }
    }

    int g = lane >> 2, q = lane & 3;
    float* pdb = g_buf + O_PD + (size_t)b * NP * NP;
#pragma unroll
    for (int mi = 0; mi < 4; mi++)
#pragma unroll
        for (int ni = 0; ni < 4; ni++) {
            int r0 = mw * 64 + mi * 16 + g;
            int c0 = nw * 32 + ni * 8 + q * 2;
            float xj0 = xxj_s[c0], xj1 = xxj_s[c0 + 1];
            float xi0 = xxi_s[r0], xi1 = xxi_s[r0 + 8];
            float2 v01, v23;
            v01.x = 2.f * acc[mi][ni][0] - xi0 - xj0;
            v01.y = 2.f * acc[mi][ni][1] - xi0 - xj1;
            v23.x = 2.f * acc[mi][ni][2] - xi1 - xj0;
            v23.y = 2.f * acc[mi][ni][3] - xi1 - xj1;
            *(float2*)(pdb + (size_t)(ibase + r0) * NP + jbase + c0) = v01;
            *(float2*)(pdb + (size_t)(ibase + r0 + 8) * NP + jbase + c0) = v23;
        }

    __syncthreads();
    if (ibase != jbase) {
        float* patch = (float*)(ps + 1024) + (size_t)wid * 32 * 68;
#pragma unroll
        for (int mi = 0; mi < 4; mi++)
#pragma unroll
            for (int ni = 0; ni < 4; ni++) {
                int rl = mi * 16 + g;
                int cl = ni * 8 + q * 2;
                int r0 = mw * 64 + rl, c0 = nw * 32 + cl;
                float xj0 = xxj_s[c0], xj1 = xxj_s[c0 + 1];
                float xi0 = xxi_s[r0], xi1 = xxi_s[r0 + 8];
                patch[(cl + 0) * 68 + rl]     = 2.f * acc[mi][ni][0] - xi0 - xj0;
                patch[(cl + 1) * 68 + rl]     = 2.f * acc[mi][ni][1] - xi0 - xj1;
                patch[(cl + 0) * 68 + rl + 8] = 2.f * acc[mi][ni][2] - xi1 - xj0;
                patch[(cl + 1) * 68 + rl + 8] = 2.f * acc[mi][ni][3] - xi1 - xj1;
            }
        __syncwarp();
#pragma unroll
        for (int cc = 0; cc < 32; cc++) {
            float2 val = *(float2*)(patch + cc * 68 + lane * 2);
            *(float2*)(pdb + (size_t)(jbase + nw * 32 + cc) * NP + ibase + mw * 64 + lane * 2) = val;
        }
    }
}

// ---------------- HMMA conv1x1 ----------------
// MODE 0=QKV (out fp32 [b][n][c])  2=W1-fused (K=256: x then av, out fp32 [b][o][n])
// 3=W2 (K=256, bn'd h2 input, residual, out fp32)
#define CLDA 264
#define CONV_SMEM (2 * 128 * CLDA * 2)

template<int MODE>
__global__ void __launch_bounds__(256, 1) conv_mma(const float* __restrict__ bias0,
                                                   const float* __restrict__ bias1,
                                                   const float* __restrict__ bias2,
                                                   const float* __restrict__ resid,
                                                   float* __restrict__ outp) {
    extern __shared__ char cs[];
    __half* As = (__half*)cs;
    __half* Bs = As + 128 * CLDA;
    int tid = threadIdx.x, lane = tid & 31, wid = tid >> 5;
    int b = blockIdx.z, nbase = blockIdx.x * 128;
    int yb = blockIdx.y;

    const __half* WH = reinterpret_cast<const __half*>(g_buf + O_WH);
    const __half* WM = reinterpret_cast<const __half*>(g_buf + O_WM2);
    int woff, wstride, obase = 0;
    if (MODE == 0)      { woff = yb * 16384; wstride = 128; }
    else if (MODE == 2) { woff = WOFF_1 + yb * 128 * 256; wstride = 256; obase = yb * 128; }
    else                { woff = WOFF_2; wstride = 256; }
    const int KCH = (MODE >= 2) ? 2 : 1;

    float acc[4][4][4];
#pragma unroll
    for (int a1 = 0; a1 < 4; a1++)
#pragma unroll
        for (int a2 = 0; a2 < 4; a2++)
#pragma unroll
            for (int a3 = 0; a3 < 4; a3++) acc[a1][a2][a3] = 0.f;

    int mw = wid & 1, nw = wid >> 1;
    int lrow = lane & 15, lcol8 = (lane >> 4) * 8;
    uint32_t a_s0 = smem_u32(As + (size_t)(mw * 64) * CLDA);
    uint32_t b_s0 = smem_u32(Bs + (size_t)(nw * 32) * CLDA);

#pragma unroll
    for (int kc = 0; kc < KCH; kc++) {
        const __half* wsh = WH + woff + kc * 128;
        const __half* wsm = WM + woff + kc * 128;
#pragma unroll
        for (int idx = tid; idx < 2048; idx += 256) {
            int row = idx >> 4, ch = idx & 15;
            *(uint4*)(As + (size_t)row * CLDA + ch * 8) =
                *(const uint4*)(wsh + (size_t)row * wstride + ch * 8);
            *(uint4*)(As + (size_t)row * CLDA + 128 + ch * 8) =
                *(const uint4*)(wsm + (size_t)row * wstride + ch * 8);
        }
        const __half *bh, *bm; int bstr;
        if (MODE == 0) { bh = (const __half*)(g_buf + O_XH); bm = (const __half*)(g_buf + O_XM); bstr = 128; }
        else if (MODE == 2) {
            if (kc == 0) { bh = (const __half*)(g_buf + O_XH); bm = (const __half*)(g_buf + O_XM); }
            else         { bh = (const __half*)(g_buf + O_AVH); bm = (const __half*)(g_buf + O_AVM); }
            bstr = 128;
        } else {
            bh = (const __half*)(g_buf + O_H2H) + kc * 128;
            bm = (const __half*)(g_buf + O_H2M) + kc * 128;
            bstr = 256;
        }
        const __half* bhp = bh + (size_t)(b * NP + nbase) * bstr;
        const __half* bmp = bm + (size_t)(b * NP + nbase) * bstr;
#pragma unroll
        for (int idx = tid; idx < 2048; idx += 256) {
            int row = idx >> 4, ch = idx & 15;
            *(uint4*)(Bs + (size_t)row * CLDA + ch * 8) =
                *(const uint4*)(bhp + (size_t)row * bstr + ch * 8);
            *(uint4*)(Bs + (size_t)row * CLDA + 128 + ch * 8) =
                *(const uint4*)(bmp + (size_t)row * bstr + ch * 8);
        }
        __syncthreads();

        const int ACOL[3] = {0, 0, 128};
        const int BCOL[3] = {0, 128, 0};
#pragma unroll
        for (int seg = 0; seg < 3; seg++) {
#pragma unroll
            for (int k16 = 0; k16 < 8; k16++) {
                int akc = ACOL[seg] + k16 * 16 + lcol8;
                int bkc = BCOL[seg] + k16 * 16 + lcol8;
                uint32_t arg[4][4];
#pragma unroll
                for (int mi = 0; mi < 4; mi++) {
                    uint32_t addr = a_s0 + (uint32_t)(((mi * 16 + lrow) * CLDA + akc) * 2);
                    asm volatile("ldmatrix.sync.aligned.m8n8.x4.shared.b16 {%0,%1,%2,%3}, [%4];"
                                 : "=r"(arg[mi][0]), "=r"(arg[mi][1]), "=r"(arg[mi][2]), "=r"(arg[mi][3])
                                 : "r"(addr));
                }
                uint32_t brg[2][4];
#pragma unroll
                for (int nh = 0; nh < 2; nh++) {
                    uint32_t addr = b_s0 + (uint32_t)(((nh * 16 + lrow) * CLDA + bkc) * 2);
                    asm volatile("ldmatrix.sync.aligned.m8n8.x4.shared.b16 {%0,%1,%2,%3}, [%4];"
                                 : "=r"(brg[nh][0]), "=r"(brg[nh][1]), "=r"(brg[nh][2]), "=r"(brg[nh][3])
                                 : "r"(addr));
                }
#pragma unroll
                for (int mi = 0; mi < 4; mi++)
#pragma unroll
                    for (int ni = 0; ni < 4; ni++) {
                        uint32_t b0 = brg[ni >> 1][ni & 1];
                        uint32_t b1 = brg[ni >> 1][2 + (ni & 1)];
                        asm volatile(
                            "mma.sync.aligned.m16n8k16.row.col.f32.f16.f16.f32 "
                            "{%0,%1,%2,%3}, {%4,%5,%6,%7}, {%8,%9}, {%0,%1,%2,%3};"
                            : "+f"(acc[mi][ni][0]), "+f"(acc[mi][ni][1]),
                              "+f"(acc[mi][ni][2]), "+f"(acc[mi][ni][3])
                            : "r"(arg[mi][0]), "r"(arg[mi][1]), "r"(arg[mi][2]), "r"(arg[mi][3]),
                              "r"(b0), "r"(b1));
                    }
            }
        }
        __syncthreads();
    }

    int g = lane >> 2, q = lane & 3;
    if (MODE == 0) {
        const float* bias_ = (yb == 0 ? bias0 : yb == 1 ? bias1 : bias2);
        float* patch = (float*)cs + (size_t)wid * 32 * 68;
#pragma unroll
        for (int mi = 0; mi < 4; mi++)
#pragma unroll
            for (int ni = 0; ni < 4; ni++) {
                int rl = mi * 16 + g;
                int cl = ni * 8 + q * 2;
                float bs0 = bias_[mw * 64 + rl], bs1 = bias_[mw * 64 + rl + 8];
                patch[(cl + 0) * 68 + rl]     = acc[mi][ni][0] + bs0;
                patch[(cl + 1) * 68 + rl]     = acc[mi][ni][1] + bs0;
                patch[(cl + 0) * 68 + rl + 8] = acc[mi][ni][2] + bs1;
                patch[(cl + 1) * 68 + rl + 8] = acc[mi][ni][3] + bs1;
            }
        __syncwarp();
        float* Y = g_buf + O_QT + (size_t)yb * BB * NP * CC;
#pragma unroll
        for (int r = 0; r < 32; r++) {
            int n = nbase + nw * 32 + r;
            *(float2*)(Y + ((size_t)b * NP + n) * CC + mw * 64 + lane * 2) =
                *(float2*)(patch + r * 68 + lane * 2);
        }
    } else {
        const float* bias_ = bias0;
        float* Yb = outp + (size_t)b * ((MODE == 2) ? C2 * NP : CC * NP);
#pragma unroll
        for (int mi = 0; mi < 4; mi++)
#pragma unroll
            for (int ni = 0; ni < 4; ni++) {
                int r0 = obase + mw * 64 + mi * 16 + g;
                int c0 = nbase + nw * 32 + ni * 8 + q * 2;
                float bs0 = bias_[r0], bs1 = bias_[r0 + 8];
                float2 v01, v23;
                v01.x = acc[mi][ni][0] + bs0; v01.y = acc[mi][ni][1] + bs0;
                v23.x = acc[mi][ni][2] + bs1; v23.y = acc[mi][ni][3] + bs1;
                if (MODE == 3) {
                    const float* rb = resid + (size_t)b * CC * NP;
                    v01.x += rb[(size_t)r0 * NP + c0];
                    v01.y += rb[(size_t)r0 * NP + c0 + 1];
                    v23.x += rb[(size_t)(r0 + 8) * NP + c0];
                    v23.y += rb[(size_t)(r0 + 8) * NP + c0 + 1];
                }
                *(float2*)(Yb + (size_t)r0 * NP + c0) = v01;
                *(float2*)(Yb + (size_t)(r0 + 8) * NP + c0) = v23;
            }
    }
}

// ---------------- warp-per-row top-20 ----------------
#define TOPK_SMEM (8 * 2048 * 4)
__global__ void __launch_bounds__(256) topk_kernel() {
    extern __shared__ float srows[];
    const unsigned FULL = 0xffffffffu;
    int tid = threadIdx.x, lane = tid & 31, wid = tid >> 5;
    int rowbase = blockIdx.x * 8;
    const float4* g4 = (const float4*)(g_buf + O_PD + (size_t)rowbase * NP);
    float4* s4 = (float4*)srows;
#pragma unroll
    for (int i = tid; i < 8 * 512; i += 256) s4[i] = g4[i];
    __syncthreads();

    float* s = srows + wid * 2048 + lane * 64;
    float bv = -3.4e38f; int bi = 0;
#pragma unroll
    for (int k4 = 0; k4 < 16; k4++) {
        float4 vv = *(float4*)(s + k4 * 4);
        if (vv.x > bv) { bv = vv.x; bi = k4 * 4 + 0; }
        if (vv.y > bv) { bv = vv.y; bi = k4 * 4 + 1; }
        if (vv.z > bv) { bv = vv.z; bi = k4 * 4 + 2; }
        if (vv.w > bv) { bv = vv.w; bi = k4 * 4 + 3; }
    }
    int gbase = lane * 64;
    int* idxout = reinterpret_cast<int*>(g_buf + O_IDX) + (size_t)(rowbase + wid) * KNN;

    for (int it = 0; it < KNN; it++) {
        float cv = bv; int ci = gbase + bi;
#pragma unroll
        for (int off = 16; off; off >>= 1) {
            float ov = __shfl_down_sync(FULL, cv, off);
            int oi = __shfl_down_sync(FULL, ci, off);
            if (ov > cv || (ov == cv && oi < ci)) { cv = ov; ci = oi; }
        }
        ci = __shfl_sync(FULL, ci, 0);
        if (lane == 0) idxout[it] = ci;
        if ((ci >> 6) == lane) {
            s[ci & 63] = -3.4e38f;
            bv = -3.4e38f; bi = 0;
#pragma unroll
            for (int k4 = 0; k4 < 16; k4++) {
                float4 vv = *(float4*)(s + k4 * 4);
                if (vv.x > bv) { bv = vv.x; bi = k4 * 4 + 0; }
                if (vv.y > bv) { bv = vv.y; bi = k4 * 4 + 1; }
                if (vv.z > bv) { bv = vv.z; bi = k4 * 4 + 2; }
                if (vv.w > bv) { bv = vv.w; bi = k4 * 4 + 3; }
            }
        }
    }
}

// ---------------- sparse mutual-kNN attention: one warp per (b,n) ----------------
__global__ void attn_kernel() {
    const unsigned FULL = 0xffffffffu;
    int gwarp = (blockIdx.x * blockDim.x + threadIdx.x) >> 5;
    int lane = threadIdx.x & 31;
    int b = gwarp / NP, n = gwarp - b * NP;

    const float* qT = g_buf + O_QT;
    const float* kT = g_buf + O_QT + BB * NP * CC;
    const float* vT = g_buf + O_QT + 2 * BB * NP * CC;
    const int* idx = reinterpret_cast<const int*>(g_buf + O_IDX);

    const float* qrow = qT + ((size_t)b * NP + n) * CC;
    float q0 = qrow[lane], q1 = qrow[lane + 32], q2 = qrow[lane + 64], q3 = qrow[lane + 96];

    int mj = 0, act = 0;
    if (lane < KNN) {
        mj = idx[(b * NP + n) * KNN + lane];
        const int* lst = idx + (size_t)(b * NP + mj) * KNN;
#pragma unroll
        for (int tt = 0; tt < KNN; tt++) act |= (lst[tt] == n);
    }
    unsigned amask = __ballot_sync(FULL, act);

    float sc[4] = {0.f, 0.f, 0.f, 0.f};
    for (int jj = 0; jj < KNN; jj++) {
        if (!((amask >> jj) & 1)) continue;
        int m = __shfl_sync(FULL, mj, jj);
        const float* krow = kT + ((size_t)b * NP + m) * CC;
        float p0 = q0 * krow[lane], p1 = q1 * krow[lane + 32];
        float p2 = q2 * krow[lane + 64], p3 = q3 * krow[lane + 96];
#pragma unroll
        for (int off = 16; off; off >>= 1) {
            p0 += __shfl_xor_sync(FULL, p0, off);
            p1 += __shfl_xor_sync(FULL, p1, off);
            p2 += __shfl_xor_sync(FULL, p2, off);
            p3 += __shfl_xor_sync(FULL, p3, off);
        }
        if (lane == jj) { sc[0] = p0; sc[1] = p1; sc[2] = p2; sc[3] = p3; }
    }

    const float scale = 0.17677669529663687f;
    bool live = (lane < KNN) && ((amask >> lane) & 1);
    float p[4];
#pragma unroll
    for (int hh = 0; hh < 4; hh++) {
        float v = live ? sc[hh] * scale : -3.4e38f;
        float mx = v;
#pragma unroll
        for (int off = 16; off; off >>= 1) mx = fmaxf(mx, __shfl_xor_sync(FULL, mx, off));
        float e = live ? expf(v - mx) : 0.f;
        float sm = e;
#pragma unroll
        for (int off = 16; off; off >>= 1) sm += __shfl_xor_sync(FULL, sm, off);
        p[hh] = e / sm;
    }

    float a0 = 0.f, a1 = 0.f, a2 = 0.f, a3 = 0.f;
    for (int jj = 0; jj < KNN; jj++) {
        if (!((amask >> jj) & 1)) continue;
        int m = __shfl_sync(FULL, mj, jj);
        float w0 = __shfl_sync(FULL, p[0], jj);
        float w1 = __shfl_sync(FULL, p[1], jj);
        float w2 = __shfl_sync(FULL, p[2], jj);
        float w3 = __shfl_sync(FULL, p[3], jj);
        const float* vrow = vT + ((size_t)b * NP + m) * CC;
        a0 = fmaf(w0, vrow[lane], a0);
        a1 = fmaf(w1, vrow[lane + 32], a1);
        a2 = fmaf(w2, vrow[lane + 64], a2);
        a3 = fmaf(w3, vrow[lane + 96], a3);
    }
    __half* avh = (__half*)(g_buf + O_AVH);
    __half* avm = (__half*)(g_buf + O_AVM);
    size_t o = ((size_t)b * NP + n) * CC;
    float vals[4] = {a0, a1, a2, a3};
#pragma unroll
    for (int c = 0; c < 4; c++) {
        __half hh = __float2half_rn(vals[c]);
        avh[o + c * 32 + lane] = hh;
        avm[o + c * 32 + lane] = __float2half_rn(vals[c] - __half2float(hh));
    }
}

// ---------------- batchnorm statistics ----------------
__global__ void bn_stats_kernel() {
    __shared__ float ss[256], ss2[256];
    int c = blockIdx.x, tid = threadIdx.x;
    float s = 0.f, s2 = 0.f;
    for (int bn = tid; bn < BB * NP; bn += 256) {
        int b = bn >> 11, n = bn & (NP - 1);
        float v = g_buf[O_H + (size_t)b * C2 * NP + (size_t)c * NP + n];
        s += v; s2 = fmaf(v, v, s2);
    }
    ss[tid] = s; ss2[tid] = s2;
    __syncthreads();
    for (int off = 128; off; off >>= 1) {
        if (tid < off) { ss[tid] += ss[tid + off]; ss2[tid] += ss2[tid + off]; }
        __syncthreads();
    }
    if (tid == 0) {
        float inv = 1.f / (BB * NP);
        float mu = ss[0] * inv;
        float var = ss2[0] * inv - mu * mu;
        g_buf[O_MU + c] = mu;
        g_buf[O_ISTD + c] = rsqrtf(var + 1e-5f);
    }
}

// ---------------- bn+relu + transpose + split ----------------
__global__ void bnrelu_kernel(const float* __restrict__ gamma, const float* __restrict__ beta) {
    __shared__ float t[32][33];
    int b = blockIdx.z, cbase = blockIdx.y * 32, nbase = blockIdx.x * 32;
    int tid = threadIdx.x;
    const float* hsrc = g_buf + O_H + (size_t)b * C2 * NP;
#pragma unroll
    for (int i = tid; i < 1024; i += 256) {
        int c = i >> 5, n = i & 31;
        t[c][n] = hsrc[(size_t)(cbase + c) * NP + nbase + n];
    }
    __syncthreads();
    __half* h2h = (__half*)(g_buf + O_H2H);
    __half* h2m = (__half*)(g_buf + O_H2M);
#pragma unroll
    for (int i = tid; i < 1024; i += 256) {
        int n = i >> 5, c = i & 31;
        int cg = cbase + c;
        float v = t[c][n];
        v = fmaxf(fmaf((v - g_buf[O_MU + cg]) * g_buf[O_ISTD + cg], gamma[cg], beta[cg]), 0.f);
        __half hh = __float2half_rn(v);
        size_t o = ((size_t)b * NP + nbase + n) * C2 + cg;
        h2h[o] = hh;
        h2m[o] = __float2half_rn(v - __half2float(hh));
    }
}

// ---------------- launch ----------------
extern "C" void kernel_launch(void* const* d_in, const int* in_sizes, int n_in,
                              void* d_out, int out_size) {
    (void)in_sizes; (void)n_in; (void)out_size;
    const float* x     = (const float*)d_in[0];
    const float* wq    = (const float*)d_in[1];
    const float* bq    = (const float*)d_in[2];
    const float* wk    = (const float*)d_in[3];
    const float* bk    = (const float*)d_in[4];
    const float* wv    = (const float*)d_in[5];
    const float* bv    = (const float*)d_in[6];
    const float* wm    = (const float*)d_in[7];
    const float* bm    = (const float*)d_in[8];
    const float* w1    = (const float*)d_in[9];
    const float* b1    = (const float*)d_in[10];
    const float* gamma = (const float*)d_in[11];
    const float* beta  = (const float*)d_in[12];
    const float* w2    = (const float*)d_in[13];
    const float* b2    = (const float*)d_in[14];
    float* out = (float*)d_out;

    float* base = nullptr;
    cudaGetSymbolAddress((void**)&base, g_buf);
    float* p_h = base + O_H;
    float* p_b1p = base + O_B1P;

    static cudaStream_t s2 = nullptr, s3 = nullptr;
    static cudaEvent_t evFork = nullptr, evPrep = nullptr, evXX = nullptr,
                       evQKV = nullptr, evW = nullptr;
    if (s2 == nullptr) {
        cudaStreamCreateWithFlags(&s2, cudaStreamNonBlocking);
        cudaStreamCreateWithFlags(&s3, cudaStreamNonBlocking);
        cudaEventCreateWithFlags(&evFork, cudaEventDisableTiming);
        cudaEventCreateWithFlags(&evPrep, cudaEventDisableTiming);
        cudaEventCreateWithFlags(&evXX, cudaEventDisableTiming);
        cudaEventCreateWithFlags(&evQKV, cudaEventDisableTiming);
        cudaEventCreateWithFlags(&evW, cudaEventDisableTiming);
    }

    cudaFuncSetAttribute(pd_mma_kernel, cudaFuncAttributeMaxDynamicSharedMemorySize, PD_SMEM);
    cudaFuncSetAttribute(conv_mma<0>, cudaFuncAttributeMaxDynamicSharedMemorySize, CONV_SMEM);
    cudaFuncSetAttribute(conv_mma<2>, cudaFuncAttributeMaxDynamicSharedMemorySize, CONV_SMEM);
    cudaFuncSetAttribute(conv_mma<3>, cudaFuncAttributeMaxDynamicSharedMemorySize, CONV_SMEM);
    cudaFuncSetAttribute(topk_kernel, cudaFuncAttributeMaxDynamicSharedMemorySize, TOPK_SMEM);

    // fork point
    cudaEventRecord(evFork, 0);
    cudaStreamWaitEvent(s2, evFork, 0);
    cudaStreamWaitEvent(s3, evFork, 0);

    // s2: weight split -> (wait prep) qkv conv -> weight fuse
    wsplit_kernel<<<(WTOT + 255) / 256, 256, 0, s2>>>(wq, wk, wv, wm, w1, w2);
    // s3: xx
    xx_kernel<<<(BB * NP + 255) / 256, 256, 0, s3>>>(x);
    cudaEventRecord(evXX, s3);
    // main: prep
    prep_kernel<<<dim3(NP / 64, CC / 32, BB), 256>>>(x);
    cudaEventRecord(evPrep, 0);

    cudaStreamWaitEvent(s2, evPrep, 0);
    conv_mma<0><<<dim3(NP / 128, 3, BB), 256, CONV_SMEM, s2>>>(bq, bk, bv, nullptr, nullptr);
    cudaEventRecord(evQKV, s2);
    wfuse_kernel<<<256, 128, 0, s2>>>(w1, wm, bm, b1);
    cudaEventRecord(evW, s2);

    // main: pd -> topk (needs prep + xx)
    cudaStreamWaitEvent(0, evXX, 0);
    pd_mma_kernel<<<dim3(136, BB), 256, PD_SMEM>>>();
    topk_kernel<<<BB * NP / 8, 256, TOPK_SMEM>>>();

    cudaStreamWaitEvent(0, evQKV, 0);
    attn_kernel<<<BB * NP / 8, 256>>>();

    cudaStreamWaitEvent(0, evW, 0);
    conv_mma<2><<<dim3(NP / 128, 2, BB), 256, CONV_SMEM>>>(p_b1p, nullptr, nullptr, nullptr, p_h);

    bn_stats_kernel<<<C2, 256>>>();
    bnrelu_kernel<<<dim3(NP / 32, C2 / 32, BB), 256>>>(gamma, beta);

    conv_mma<3><<<dim3(NP / 128, 1, BB), 256, CONV_SMEM>>>(b2, nullptr, nullptr, x, out);
}